// round 2
// baseline (speedup 1.0000x reference)
#include <cuda_runtime.h>
#include <cstdint>

#define B_  8
#define S_  2048
#define E_  2048
#define H_  16
#define D_  128
#define BH_ (B_ * H_)
#define NCHUNK_ 4
#define CHUNK_S_ (S_ / NCHUNK_)   // 512
#define EPS_ 1e-6f

// ---------------- scratch (__device__ globals; no allocation allowed) ----------------
__device__ float g_kvp[(size_t)BH_ * NCHUNK_ * D_ * D_];  // partial kv  (32 MB)
__device__ float g_ksp[(size_t)BH_ * NCHUNK_ * D_];       // partial ksum
__device__ float g_kv [(size_t)BH_ * D_ * D_];            // kv = pk^T v (8 MB)
__device__ float g_ks [(size_t)BH_ * D_];                 // ksum
__device__ float g_comb[(size_t)B_ * S_ * E_];            // combined heads (128 MB)

__device__ __forceinline__ float phi_(float y) {          // elu(y)+1
    return (y > 0.f) ? (y + 1.f) : expf(y);
}

// ---------------------------------------------------------------------------
// Kernel A: fused K-proj, V-proj, phi, partial kv & ksum accumulation.
// grid = (NCHUNK, BH), block 256. Each block handles 512 seq rows in 16
// sub-tiles of 32 rows; K/V tiles never leave SMEM.
// ---------------------------------------------------------------------------
__global__ void __launch_bounds__(256) fused_kv_kernel(const float* __restrict__ x,
                                                       const float* __restrict__ Wk,
                                                       const float* __restrict__ Wv) {
    const int chunk = blockIdx.x;
    const int bh    = blockIdx.y;
    const int b = bh / H_, h = bh % H_;

    const float* Wkh = Wk + (size_t)h * D_ * D_;
    const float* Wvh = Wv + (size_t)h * D_ * D_;
    const float* Xb  = x + (size_t)b * S_ * E_ + (size_t)h * D_;

    __shared__ float Wks[8][128];
    __shared__ float Wvs[8][128];
    __shared__ float Xs[32][8];
    __shared__ float Kt[32][128];
    __shared__ float Vt[32][128];

    const int tid = threadIdx.x;
    const int tx = tid & 15;     // col group: cols tx*8 .. +7
    const int ty = tid >> 4;     // 16 row groups

    float acc_kv[8][8];
#pragma unroll
    for (int r = 0; r < 8; r++)
#pragma unroll
        for (int c = 0; c < 8; c++) acc_kv[r][c] = 0.f;
    float ksum_acc = 0.f;

    for (int sub = 0; sub < CHUNK_S_ / 32; sub++) {
        const int s0 = chunk * CHUNK_S_ + sub * 32;

        // ---- phase 1: project 32 rows of K and V into SMEM ----
        float acc_k[2][8], acc_v[2][8];
#pragma unroll
        for (int r = 0; r < 2; r++)
#pragma unroll
            for (int c = 0; c < 8; c++) { acc_k[r][c] = 0.f; acc_v[r][c] = 0.f; }

        for (int k0 = 0; k0 < D_; k0 += 8) {
            {   // load X sub-tile (32 x 8), one element per thread
                int r = tid >> 3, c = tid & 7;
                Xs[r][c] = Xb[(size_t)(s0 + r) * E_ + k0 + c];
            }
#pragma unroll
            for (int i = tid; i < 8 * 128; i += 256) {
                int r = i >> 7, c = i & 127;
                Wks[r][c] = Wkh[(k0 + r) * D_ + c];
                Wvs[r][c] = Wvh[(k0 + r) * D_ + c];
            }
            __syncthreads();
#pragma unroll
            for (int kk = 0; kk < 8; kk++) {
                float a0 = Xs[ty * 2][kk];
                float a1 = Xs[ty * 2 + 1][kk];
                float4 k0v = *(const float4*)&Wks[kk][tx * 8];
                float4 k1v = *(const float4*)&Wks[kk][tx * 8 + 4];
                float4 v0v = *(const float4*)&Wvs[kk][tx * 8];
                float4 v1v = *(const float4*)&Wvs[kk][tx * 8 + 4];
                float kb[8] = {k0v.x, k0v.y, k0v.z, k0v.w, k1v.x, k1v.y, k1v.z, k1v.w};
                float vb[8] = {v0v.x, v0v.y, v0v.z, v0v.w, v1v.x, v1v.y, v1v.z, v1v.w};
#pragma unroll
                for (int c = 0; c < 8; c++) {
                    acc_k[0][c] = fmaf(a0, kb[c], acc_k[0][c]);
                    acc_k[1][c] = fmaf(a1, kb[c], acc_k[1][c]);
                    acc_v[0][c] = fmaf(a0, vb[c], acc_v[0][c]);
                    acc_v[1][c] = fmaf(a1, vb[c], acc_v[1][c]);
                }
            }
            __syncthreads();
        }
#pragma unroll
        for (int r = 0; r < 2; r++)
#pragma unroll
            for (int c = 0; c < 8; c++) {
                Kt[ty * 2 + r][tx * 8 + c] = phi_(acc_k[r][c]);
                Vt[ty * 2 + r][tx * 8 + c] = acc_v[r][c];
            }
        __syncthreads();

        // ---- phase 2: ksum partial + kv partial accumulation ----
        if (tid < 128) {
#pragma unroll
            for (int r = 0; r < 32; r++) ksum_acc += Kt[r][tid];
        }
#pragma unroll 4
        for (int ss = 0; ss < 32; ss++) {
            float4 a0 = *(const float4*)&Kt[ss][ty * 8];
            float4 a1 = *(const float4*)&Kt[ss][ty * 8 + 4];
            float4 b0 = *(const float4*)&Vt[ss][tx * 8];
            float4 b1 = *(const float4*)&Vt[ss][tx * 8 + 4];
            float a[8] = {a0.x, a0.y, a0.z, a0.w, a1.x, a1.y, a1.z, a1.w};
            float bb[8] = {b0.x, b0.y, b0.z, b0.w, b1.x, b1.y, b1.z, b1.w};
#pragma unroll
            for (int r = 0; r < 8; r++)
#pragma unroll
                for (int c = 0; c < 8; c++) acc_kv[r][c] = fmaf(a[r], bb[c], acc_kv[r][c]);
        }
        __syncthreads();
    }

    float* kvp = g_kvp + ((size_t)bh * NCHUNK_ + chunk) * D_ * D_;
#pragma unroll
    for (int r = 0; r < 8; r++)
#pragma unroll
        for (int c = 0; c < 8; c++)
            kvp[(size_t)(ty * 8 + r) * D_ + tx * 8 + c] = acc_kv[r][c];
    if (tid < 128)
        g_ksp[((size_t)bh * NCHUNK_ + chunk) * D_ + tid] = ksum_acc;
}

// ---------------------------------------------------------------------------
// Kernel A2: reduce the NCHUNK partials.  grid = BH, block 256.
// ---------------------------------------------------------------------------
__global__ void reduce_kernel() {
    const int bh = blockIdx.x;
    const int tid = threadIdx.x;
    const float* kvp = g_kvp + (size_t)bh * NCHUNK_ * D_ * D_;
    float* kv = g_kv + (size_t)bh * D_ * D_;
    for (int i = tid; i < D_ * D_; i += 256) {
        float s = 0.f;
#pragma unroll
        for (int c = 0; c < NCHUNK_; c++) s += kvp[(size_t)c * D_ * D_ + i];
        kv[i] = s;
    }
    if (tid < D_) {
        const float* ksp = g_ksp + (size_t)bh * NCHUNK_ * D_;
        float s = 0.f;
#pragma unroll
        for (int c = 0; c < NCHUNK_; c++) s += ksp[(size_t)c * D_ + tid];
        g_ks[(size_t)bh * D_ + tid] = s;
    }
}

// ---------------------------------------------------------------------------
// Kernel B: fused Q-proj + phi + ctx = (pq @ kv) / (pq . ksum + eps),
// scattered into combined-head layout.  grid = (S/64, BH), block 256.
// ---------------------------------------------------------------------------
__global__ void __launch_bounds__(256) fused_ctx_kernel(const float* __restrict__ x,
                                                        const float* __restrict__ Wq) {
    const int stile = blockIdx.x;
    const int bh    = blockIdx.y;
    const int b = bh / H_, h = bh % H_;

    const float* Wqh = Wq + (size_t)h * D_ * D_;
    const float* Xb  = x + (size_t)b * S_ * E_ + (size_t)h * D_;
    const float* kv  = g_kv + (size_t)bh * D_ * D_;

    __shared__ float Qt[64][128];      // phi(q) tile
    __shared__ float Wbuf[16][128];    // Wq chunk, then kv chunk
    __shared__ float Xs[64][16];
    __shared__ float ksum_s[128];
    __shared__ float den_s[64];

    const int tid = threadIdx.x;
    const int tx = tid & 15;
    const int ty = tid >> 4;
    const int s0 = stile * 64;

    if (tid < 128) ksum_s[tid] = g_ks[(size_t)bh * D_ + tid];

    // ---- phase 1: Q projection into Qt ----
    float acc[4][8];
#pragma unroll
    for (int r = 0; r < 4; r++)
#pragma unroll
        for (int c = 0; c < 8; c++) acc[r][c] = 0.f;

    for (int k0 = 0; k0 < D_; k0 += 16) {
#pragma unroll
        for (int i = tid; i < 64 * 16; i += 256) {
            int r = i >> 4, c = i & 15;
            Xs[r][c] = Xb[(size_t)(s0 + r) * E_ + k0 + c];
        }
#pragma unroll
        for (int i = tid; i < 16 * 128; i += 256) {
            int r = i >> 7, c = i & 127;
            Wbuf[r][c] = Wqh[(k0 + r) * D_ + c];
        }
        __syncthreads();
#pragma unroll
        for (int kk = 0; kk < 16; kk++) {
            float a[4];
#pragma unroll
            for (int r = 0; r < 4; r++) a[r] = Xs[ty * 4 + r][kk];
            float4 b0 = *(const float4*)&Wbuf[kk][tx * 8];
            float4 b1 = *(const float4*)&Wbuf[kk][tx * 8 + 4];
            float bb[8] = {b0.x, b0.y, b0.z, b0.w, b1.x, b1.y, b1.z, b1.w};
#pragma unroll
            for (int r = 0; r < 4; r++)
#pragma unroll
                for (int c = 0; c < 8; c++) acc[r][c] = fmaf(a[r], bb[c], acc[r][c]);
        }
        __syncthreads();
    }
#pragma unroll
    for (int r = 0; r < 4; r++)
#pragma unroll
        for (int c = 0; c < 8; c++)
            Qt[ty * 4 + r][tx * 8 + c] = phi_(acc[r][c]);
    __syncthreads();

    // ---- den: pq . ksum per row ----
    if (tid < 64) {
        float d = 0.f;
#pragma unroll
        for (int c = 0; c < 128; c++) d = fmaf(Qt[tid][c], ksum_s[c], d);
        den_s[tid] = d;
    }

    // ---- phase 2: ctx = Qt @ kv ----
#pragma unroll
    for (int r = 0; r < 4; r++)
#pragma unroll
        for (int c = 0; c < 8; c++) acc[r][c] = 0.f;

    for (int k0 = 0; k0 < D_; k0 += 16) {
#pragma unroll
        for (int i = tid; i < 16 * 128; i += 256) {
            int r = i >> 7, c = i & 127;
            Wbuf[r][c] = kv[(size_t)(k0 + r) * D_ + c];
        }
        __syncthreads();
#pragma unroll
        for (int kk = 0; kk < 16; kk++) {
            float a[4];
#pragma unroll
            for (int r = 0; r < 4; r++) a[r] = Qt[ty * 4 + r][k0 + kk];
            float4 b0 = *(const float4*)&Wbuf[kk][tx * 8];
            float4 b1 = *(const float4*)&Wbuf[kk][tx * 8 + 4];
            float bb[8] = {b0.x, b0.y, b0.z, b0.w, b1.x, b1.y, b1.z, b1.w};
#pragma unroll
            for (int r = 0; r < 4; r++)
#pragma unroll
                for (int c = 0; c < 8; c++) acc[r][c] = fmaf(a[r], bb[c], acc[r][c]);
        }
        __syncthreads();
    }

#pragma unroll
    for (int r = 0; r < 4; r++) {
        const int srow = s0 + ty * 4 + r;
        const float inv = 1.f / (den_s[ty * 4 + r] + EPS_);
        float* out = g_comb + ((size_t)b * S_ + srow) * E_ + h * D_ + tx * 8;
#pragma unroll
        for (int c = 0; c < 8; c++) out[c] = acc[r][c] * inv;
    }
}

// ---------------------------------------------------------------------------
// Kernel C: out = combined(16384 x 2048) @ Wo(2048 x 2048) + bo.
// grid = (E/128, B*S/128), block 256, 128x128x16 tiles, 8x8 per thread.
// ---------------------------------------------------------------------------
__global__ void __launch_bounds__(256, 2) out_kernel(const float* __restrict__ Wo,
                                                     const float* __restrict__ bo,
                                                     float* __restrict__ out) {
    const int col0 = blockIdx.x * 128;
    const int row0 = blockIdx.y * 128;

    __shared__ float As[128][16];
    __shared__ float Bs[16][128];

    const int tid = threadIdx.x;
    const int tx = tid & 15;
    const int ty = tid >> 4;

    float acc[8][8];
#pragma unroll
    for (int r = 0; r < 8; r++)
#pragma unroll
        for (int c = 0; c < 8; c++) acc[r][c] = 0.f;

    for (int k0 = 0; k0 < E_; k0 += 16) {
#pragma unroll
        for (int i = tid; i < 128 * 16; i += 256) {
            int r = i >> 4, c = i & 15;
            As[r][c] = g_comb[(size_t)(row0 + r) * E_ + k0 + c];
        }
#pragma unroll
        for (int i = tid; i < 16 * 128; i += 256) {
            int r = i >> 7, c = i & 127;
            Bs[r][c] = Wo[(size_t)(k0 + r) * E_ + col0 + c];
        }
        __syncthreads();
#pragma unroll
        for (int kk = 0; kk < 16; kk++) {
            float a[8];
#pragma unroll
            for (int r = 0; r < 8; r++) a[r] = As[ty * 8 + r][kk];
            float4 b0 = *(const float4*)&Bs[kk][tx * 8];
            float4 b1 = *(const float4*)&Bs[kk][tx * 8 + 4];
            float bb[8] = {b0.x, b0.y, b0.z, b0.w, b1.x, b1.y, b1.z, b1.w};
#pragma unroll
            for (int r = 0; r < 8; r++)
#pragma unroll
                for (int c = 0; c < 8; c++) acc[r][c] = fmaf(a[r], bb[c], acc[r][c]);
        }
        __syncthreads();
    }

    float bias[8];
#pragma unroll
    for (int c = 0; c < 8; c++) bias[c] = bo[col0 + tx * 8 + c];
#pragma unroll
    for (int r = 0; r < 8; r++) {
        float* o = out + (size_t)(row0 + ty * 8 + r) * E_ + col0 + tx * 8;
#pragma unroll
        for (int c = 0; c < 8; c++) o[c] = acc[r][c] + bias[c];
    }
}

// ---------------------------------------------------------------------------
extern "C" void kernel_launch(void* const* d_in, const int* in_sizes, int n_in,
                              void* d_out, int out_size) {
    const float* x  = (const float*)d_in[0];
    const float* Wq = (const float*)d_in[1];
    const float* Wk = (const float*)d_in[2];
    const float* Wv = (const float*)d_in[3];
    const float* Wo = (const float*)d_in[4];
    const float* bo = (const float*)d_in[5];
    float* out = (float*)d_out;

    fused_kv_kernel<<<dim3(NCHUNK_, BH_), 256>>>(x, Wk, Wv);
    reduce_kernel<<<BH_, 256>>>();
    fused_ctx_kernel<<<dim3(S_ / 64, BH_), 256>>>(x, Wq);
    out_kernel<<<dim3(E_ / 128, (B_ * S_) / 128), 256>>>(Wo, bo, out);
}

// round 5
// speedup vs baseline: 1.5782x; 1.5782x over previous
#include <cuda_runtime.h>
#include <mma.h>
#include <cstdint>

using namespace nvcuda;

#define B_  8
#define S_  2048
#define E_  2048
#define H_  16
#define D_  128
#define BH_ (B_ * H_)
#define NCHUNK_ 4
#define CHUNK_S_ (S_ / NCHUNK_)   // 512
#define EPS_ 1e-6f

typedef wmma::fragment<wmma::matrix_a, 16, 16, 8, wmma::precision::tf32, wmma::row_major> AFrag;
typedef wmma::fragment<wmma::matrix_a, 16, 16, 8, wmma::precision::tf32, wmma::col_major> ATFrag;
typedef wmma::fragment<wmma::matrix_b, 16, 16, 8, wmma::precision::tf32, wmma::row_major> BFrag;
typedef wmma::fragment<wmma::accumulator, 16, 16, 8, float> CFrag;

template <typename F>
__device__ __forceinline__ void to_tf32(F& f) {
#pragma unroll
    for (int i = 0; i < f.num_elements; i++) f.x[i] = wmma::__float_to_tf32(f.x[i]);
}

__device__ __forceinline__ float phi_(float y) { return (y > 0.f) ? (y + 1.f) : expf(y); }

// ---------------- scratch (__device__ globals; no allocation allowed) ----------------
__device__ float g_kvp[(size_t)BH_ * NCHUNK_ * D_ * D_];
__device__ float g_ksp[(size_t)BH_ * NCHUNK_ * D_];
__device__ float g_kv [(size_t)BH_ * D_ * D_];
__device__ float g_ks [(size_t)BH_ * D_];
__device__ float g_comb[(size_t)B_ * S_ * E_];

// ===========================================================================
// Kernel A: fused K-proj, V-proj, phi, partial kv & ksum (tf32 wmma).
// grid = (NCHUNK, BH), block 256 (8 warps). 32-row sub-tiles; phase-1 and
// phase-2 smem overlapped in a union to stay under 48 KB static.
// ===========================================================================
union KvSmem {
    struct { float Xs[32][36]; float Wks[32][132]; float Wvs[32][132]; } p1;  // ~38.4 KB
    struct { float Kt[32][132]; float Vt[32][132]; } p2;                      // ~33.8 KB
};

__global__ void __launch_bounds__(256) fused_kv_kernel(const float* __restrict__ x,
                                                       const float* __restrict__ Wk,
                                                       const float* __restrict__ Wv) {
    __shared__ KvSmem sm;

    const int chunk = blockIdx.x;
    const int bh    = blockIdx.y;
    const int b = bh / H_, h = bh % H_;

    const float* Wkh = Wk + (size_t)h * D_ * D_;
    const float* Wvh = Wv + (size_t)h * D_ * D_;
    const float* Xb  = x + (size_t)b * S_ * E_ + (size_t)h * D_;

    const int tid  = threadIdx.x;
    const int warp = tid >> 5;
    const int lane = tid & 31;
    // phase-1 layout: wm1 in {0,1} (16-row blocks), wn1 in {0..3} (32-col blocks)
    const int wm1 = warp & 1;
    const int wn1 = warp >> 1;
    // phase-2 layout: wm2 in {0..3} (32-row blocks), wn2 in {0,1} (64-col blocks)
    const int wm2 = warp & 3;
    const int wn2 = warp >> 2;

    CFrag acc_kv[2][4];
#pragma unroll
    for (int i = 0; i < 2; i++)
#pragma unroll
        for (int j = 0; j < 4; j++) wmma::fill_fragment(acc_kv[i][j], 0.f);

    float ksum_acc = 0.f;   // warps 0-3: column warp*32+lane

    for (int sub = 0; sub < CHUNK_S_ / 32; sub++) {
        const int s0 = chunk * CHUNK_S_ + sub * 32;

        // ---- phase 1: Kt/Vt(32x128) = X(32x128) @ Wk/Wv ----
        CFrag acck[2], accv[2];
#pragma unroll
        for (int j = 0; j < 2; j++) { wmma::fill_fragment(acck[j], 0.f); wmma::fill_fragment(accv[j], 0.f); }

        for (int k0 = 0; k0 < D_; k0 += 32) {
            {   // X: 32x32 = 256 float4, one per thread
                int r = tid >> 3, c4 = (tid & 7) * 4;
                *(float4*)&sm.p1.Xs[r][c4] = *(const float4*)&Xb[(size_t)(s0 + r) * E_ + k0 + c4];
            }
#pragma unroll
            for (int t = 0; t < 4; t++) {           // Wk,Wv: 32x128
                int f4i = tid + t * 256;
                int r = f4i >> 5, c4 = (f4i & 31) * 4;
                *(float4*)&sm.p1.Wks[r][c4] = *(const float4*)&Wkh[(size_t)(k0 + r) * D_ + c4];
                *(float4*)&sm.p1.Wvs[r][c4] = *(const float4*)&Wvh[(size_t)(k0 + r) * D_ + c4];
            }
            __syncthreads();
#pragma unroll
            for (int kk = 0; kk < 4; kk++) {
                AFrag a;
                wmma::load_matrix_sync(a, &sm.p1.Xs[wm1 * 16][kk * 8], 36);
                to_tf32(a);
#pragma unroll
                for (int j = 0; j < 2; j++) {
                    BFrag bfr;
                    wmma::load_matrix_sync(bfr, &sm.p1.Wks[kk * 8][wn1 * 32 + j * 16], 132);
                    to_tf32(bfr);
                    wmma::mma_sync(acck[j], a, bfr, acck[j]);
                    wmma::load_matrix_sync(bfr, &sm.p1.Wvs[kk * 8][wn1 * 32 + j * 16], 132);
                    to_tf32(bfr);
                    wmma::mma_sync(accv[j], a, bfr, accv[j]);
                }
            }
            __syncthreads();
        }
        // phase-1 buffers dead; write phi(K), V into the overlapping p2 tiles
#pragma unroll
        for (int j = 0; j < 2; j++) {
#pragma unroll
            for (int e = 0; e < acck[j].num_elements; e++) acck[j].x[e] = phi_(acck[j].x[e]);
            wmma::store_matrix_sync(&sm.p2.Kt[wm1 * 16][wn1 * 32 + j * 16], acck[j], 132, wmma::mem_row_major);
            wmma::store_matrix_sync(&sm.p2.Vt[wm1 * 16][wn1 * 32 + j * 16], accv[j], 132, wmma::mem_row_major);
        }
        __syncthreads();

        // ---- ksum partial (warps 0-3 each own 32 columns) ----
        if (warp < 4) {
            const int col = warp * 32 + lane;
#pragma unroll 8
            for (int r = 0; r < 32; r++) ksum_acc += sm.p2.Kt[r][col];
        }

        // ---- kv += Kt^T @ Vt  (A col_major = free transpose) ----
#pragma unroll
        for (int kk = 0; kk < 4; kk++) {
            ATFrag a2[2];
#pragma unroll
            for (int i = 0; i < 2; i++) {
                wmma::load_matrix_sync(a2[i], &sm.p2.Kt[kk * 8][wm2 * 32 + i * 16], 132);
                to_tf32(a2[i]);
            }
#pragma unroll
            for (int j = 0; j < 4; j++) {
                BFrag bfr;
                wmma::load_matrix_sync(bfr, &sm.p2.Vt[kk * 8][wn2 * 64 + j * 16], 132);
                to_tf32(bfr);
#pragma unroll
                for (int i = 0; i < 2; i++) wmma::mma_sync(acc_kv[i][j], a2[i], bfr, acc_kv[i][j]);
            }
        }
        __syncthreads();   // protect p2 before next sub overwrites p1
    }

    float* kvp = g_kvp + ((size_t)bh * NCHUNK_ + chunk) * D_ * D_;
#pragma unroll
    for (int i = 0; i < 2; i++)
#pragma unroll
        for (int j = 0; j < 4; j++)
            wmma::store_matrix_sync(&kvp[(size_t)(wm2 * 32 + i * 16) * D_ + wn2 * 64 + j * 16],
                                    acc_kv[i][j], D_, wmma::mem_row_major);
    if (warp < 4)
        g_ksp[((size_t)bh * NCHUNK_ + chunk) * D_ + warp * 32 + lane] = ksum_acc;
}

// ===========================================================================
// Kernel A2: reduce the NCHUNK partials.  grid = BH, block 256.
// ===========================================================================
__global__ void reduce_kernel() {
    const int bh = blockIdx.x;
    const int tid = threadIdx.x;
    const float* kvp = g_kvp + (size_t)bh * NCHUNK_ * D_ * D_;
    float* kv = g_kv + (size_t)bh * D_ * D_;
    for (int i = tid; i < D_ * D_; i += 256) {
        float s = 0.f;
#pragma unroll
        for (int c = 0; c < NCHUNK_; c++) s += kvp[(size_t)c * D_ * D_ + i];
        kv[i] = s;
    }
    if (tid < D_) {
        const float* ksp = g_ksp + (size_t)bh * NCHUNK_ * D_;
        float s = 0.f;
#pragma unroll
        for (int c = 0; c < NCHUNK_; c++) s += ksp[(size_t)c * D_ + tid];
        g_ks[(size_t)bh * D_ + tid] = s;
    }
}

// ===========================================================================
// Kernel B: fused Q-proj + phi + ctx (tf32 wmma).  grid = (S/32, BH), 256 thr.
// 32-row tiles, all-static smem (~39 KB).
// ===========================================================================
__global__ void __launch_bounds__(256) fused_ctx_kernel(const float* __restrict__ x,
                                                        const float* __restrict__ Wq) {
    __shared__ float Xs[32][36];
    __shared__ float Ws[32][132];
    __shared__ float Qt[32][132];
    __shared__ float ksum_s[128];
    __shared__ float den_s[32];

    const int stile = blockIdx.x;
    const int bh    = blockIdx.y;
    const int b = bh / H_, h = bh % H_;

    const float* Wqh = Wq + (size_t)h * D_ * D_;
    const float* Xb  = x + (size_t)b * S_ * E_ + (size_t)h * D_;
    const float* kv  = g_kv + (size_t)bh * D_ * D_;

    const int tid  = threadIdx.x;
    const int warp = tid >> 5;
    const int wm = warp & 1;     // 16-row blocks
    const int wn = warp >> 1;    // 32-col blocks
    const int s0 = stile * 32;

    if (tid < 128) ksum_s[tid] = g_ks[(size_t)bh * D_ + tid];

    // ---- phase 1: Qt = phi(X @ Wq) ----
    CFrag acc[2];
#pragma unroll
    for (int j = 0; j < 2; j++) wmma::fill_fragment(acc[j], 0.f);

    for (int k0 = 0; k0 < D_; k0 += 32) {
        {
            int r = tid >> 3, c4 = (tid & 7) * 4;
            *(float4*)&Xs[r][c4] = *(const float4*)&Xb[(size_t)(s0 + r) * E_ + k0 + c4];
        }
#pragma unroll
        for (int t = 0; t < 4; t++) {
            int f4i = tid + t * 256;
            int r = f4i >> 5, c4 = (f4i & 31) * 4;
            *(float4*)&Ws[r][c4] = *(const float4*)&Wqh[(size_t)(k0 + r) * D_ + c4];
        }
        __syncthreads();
#pragma unroll
        for (int kk = 0; kk < 4; kk++) {
            AFrag a;
            wmma::load_matrix_sync(a, &Xs[wm * 16][kk * 8], 36);
            to_tf32(a);
#pragma unroll
            for (int j = 0; j < 2; j++) {
                BFrag bfr;
                wmma::load_matrix_sync(bfr, &Ws[kk * 8][wn * 32 + j * 16], 132);
                to_tf32(bfr);
                wmma::mma_sync(acc[j], a, bfr, acc[j]);
            }
        }
        __syncthreads();
    }
#pragma unroll
    for (int j = 0; j < 2; j++) {
#pragma unroll
        for (int e = 0; e < acc[j].num_elements; e++) acc[j].x[e] = phi_(acc[j].x[e]);
        wmma::store_matrix_sync(&Qt[wm * 16][wn * 32 + j * 16], acc[j], 132, wmma::mem_row_major);
    }
    __syncthreads();

    // ---- den, then scale Qt rows by 1/(den+eps) BEFORE the ctx GEMM ----
    if (tid < 32) {
        float dsum = 0.f;
#pragma unroll
        for (int c = 0; c < 128; c++) dsum = fmaf(Qt[tid][c], ksum_s[c], dsum);
        den_s[tid] = 1.f / (dsum + EPS_);
    }
    __syncthreads();
#pragma unroll
    for (int t = 0; t < 16; t++) {
        int i = tid + t * 256;
        int r = i >> 7, c = i & 127;
        Qt[r][c] *= den_s[r];
    }
    __syncthreads();

    // ---- phase 2: ctx = Qt_scaled @ kv -> g_comb ----
#pragma unroll
    for (int j = 0; j < 2; j++) wmma::fill_fragment(acc[j], 0.f);

    for (int k0 = 0; k0 < D_; k0 += 32) {
#pragma unroll
        for (int t = 0; t < 4; t++) {
            int f4i = tid + t * 256;
            int r = f4i >> 5, c4 = (f4i & 31) * 4;
            *(float4*)&Ws[r][c4] = *(const float4*)&kv[(size_t)(k0 + r) * D_ + c4];
        }
        __syncthreads();
#pragma unroll
        for (int kk = 0; kk < 4; kk++) {
            AFrag a;
            wmma::load_matrix_sync(a, &Qt[wm * 16][k0 + kk * 8], 132);
            to_tf32(a);
#pragma unroll
            for (int j = 0; j < 2; j++) {
                BFrag bfr;
                wmma::load_matrix_sync(bfr, &Ws[kk * 8][wn * 32 + j * 16], 132);
                to_tf32(bfr);
                wmma::mma_sync(acc[j], a, bfr, acc[j]);
            }
        }
        __syncthreads();
    }

    float* outp = g_comb + ((size_t)b * S_ + s0 + wm * 16) * E_ + h * D_ + wn * 32;
#pragma unroll
    for (int j = 0; j < 2; j++)
        wmma::store_matrix_sync(outp + j * 16, acc[j], E_, wmma::mem_row_major);
}

// ===========================================================================
// Kernel C: out = combined @ Wo + bo (tf32 wmma).
// grid = (E/128, B*S/128), block 256, 128x128x32 tiles.  Static smem 43.7 KB.
// ===========================================================================
__global__ void __launch_bounds__(256) out_kernel(const float* __restrict__ Wo,
                                                  const float* __restrict__ bo,
                                                  float* __restrict__ out) {
    __shared__ float As[128][36];
    __shared__ float Bs[32][132];
    __shared__ float BiasS[16][132];

    const int col0 = blockIdx.x * 128;
    const int row0 = blockIdx.y * 128;
    const int tid  = threadIdx.x;
    const int warp = tid >> 5;
    const int wm = warp & 3;    // rows wm*32
    const int wn = warp >> 2;   // cols wn*64

    // replicated bias tile -> init accumulators with bias
#pragma unroll
    for (int t = 0; t < 8; t++) {
        int i = tid + t * 256;
        int r = i >> 7, c = i & 127;
        BiasS[r][c] = bo[col0 + c];
    }
    __syncthreads();

    CFrag acc[2][4];
#pragma unroll
    for (int i = 0; i < 2; i++)
#pragma unroll
        for (int j = 0; j < 4; j++)
            wmma::load_matrix_sync(acc[i][j], &BiasS[0][wn * 64 + j * 16], 132, wmma::mem_row_major);
    __syncthreads();

    for (int k0 = 0; k0 < E_; k0 += 32) {
#pragma unroll
        for (int t = 0; t < 4; t++) {            // A: 128x32
            int f4i = tid + t * 256;
            int r = f4i >> 3, c4 = (f4i & 7) * 4;
            *(float4*)&As[r][c4] = *(const float4*)&g_comb[(size_t)(row0 + r) * E_ + k0 + c4];
        }
#pragma unroll
        for (int t = 0; t < 4; t++) {            // B: 32x128
            int f4i = tid + t * 256;
            int r = f4i >> 5, c4 = (f4i & 31) * 4;
            *(float4*)&Bs[r][c4] = *(const float4*)&Wo[(size_t)(k0 + r) * E_ + col0 + c4];
        }
        __syncthreads();
#pragma unroll
        for (int kk = 0; kk < 4; kk++) {
            AFrag a[2];
#pragma unroll
            for (int i = 0; i < 2; i++) {
                wmma::load_matrix_sync(a[i], &As[wm * 32 + i * 16][kk * 8], 36);
                to_tf32(a[i]);
            }
#pragma unroll
            for (int j = 0; j < 4; j++) {
                BFrag bfr;
                wmma::load_matrix_sync(bfr, &Bs[kk * 8][wn * 64 + j * 16], 132);
                to_tf32(bfr);
#pragma unroll
                for (int i = 0; i < 2; i++) wmma::mma_sync(acc[i][j], a[i], bfr, acc[i][j]);
            }
        }
        __syncthreads();
    }

#pragma unroll
    for (int i = 0; i < 2; i++)
#pragma unroll
        for (int j = 0; j < 4; j++)
            wmma::store_matrix_sync(out + (size_t)(row0 + wm * 32 + i * 16) * E_ + col0 + wn * 64 + j * 16,
                                    acc[i][j], E_, wmma::mem_row_major);
}

// ===========================================================================
extern "C" void kernel_launch(void* const* d_in, const int* in_sizes, int n_in,
                              void* d_out, int out_size) {
    const float* x  = (const float*)d_in[0];
    const float* Wq = (const float*)d_in[1];
    const float* Wk = (const float*)d_in[2];
    const float* Wv = (const float*)d_in[3];
    const float* Wo = (const float*)d_in[4];
    const float* bo = (const float*)d_in[5];
    float* out = (float*)d_out;

    fused_kv_kernel<<<dim3(NCHUNK_, BH_), 256>>>(x, Wk, Wv);
    reduce_kernel<<<BH_, 256>>>();
    fused_ctx_kernel<<<dim3(S_ / 32, BH_), 256>>>(x, Wq);
    out_kernel<<<dim3(E_ / 128, (B_ * S_) / 128), 256>>>(Wo, bo, out);
}

// round 6
// speedup vs baseline: 1.8437x; 1.1682x over previous
#include <cuda_runtime.h>
#include <mma.h>
#include <cstdint>

using namespace nvcuda;

#define B_  8
#define S_  2048
#define E_  2048
#define H_  16
#define D_  128
#define BH_ (B_ * H_)
#define NCHUNK_ 4
#define CHUNK_S_ (S_ / NCHUNK_)   // 512
#define EPS_ 1e-6f

typedef wmma::fragment<wmma::matrix_a, 16, 16, 8, wmma::precision::tf32, wmma::row_major> AFrag;
typedef wmma::fragment<wmma::matrix_a, 16, 16, 8, wmma::precision::tf32, wmma::col_major> ATFrag;
typedef wmma::fragment<wmma::matrix_b, 16, 16, 8, wmma::precision::tf32, wmma::row_major> BFrag;
typedef wmma::fragment<wmma::accumulator, 16, 16, 8, float> CFrag;

template <typename F>
__device__ __forceinline__ void to_tf32(F& f) {
#pragma unroll
    for (int i = 0; i < f.num_elements; i++) f.x[i] = wmma::__float_to_tf32(f.x[i]);
}

__device__ __forceinline__ float phi_(float y) { return (y > 0.f) ? (y + 1.f) : expf(y); }

__device__ __forceinline__ void cpasync16(void* smem, const void* gmem) {
    uint32_t s = (uint32_t)__cvta_generic_to_shared(smem);
    asm volatile("cp.async.cg.shared.global [%0], [%1], 16;" :: "r"(s), "l"(gmem));
}
#define CP_COMMIT()  asm volatile("cp.async.commit_group;")
#define CP_WAIT(N)   asm volatile("cp.async.wait_group %0;" :: "n"(N))

// ---------------- scratch (__device__ globals; no allocation allowed) ----------------
__device__ float g_kvp[(size_t)BH_ * NCHUNK_ * D_ * D_];
__device__ float g_ksp[(size_t)BH_ * NCHUNK_ * D_];
__device__ float g_kv [(size_t)BH_ * D_ * D_];
__device__ float g_ks [(size_t)BH_ * D_];
__device__ float g_comb[(size_t)B_ * S_ * E_];

// ===========================================================================
// Kernel A: fused K-proj, V-proj, phi, partial kv & ksum (tf32 wmma).
// grid = (NCHUNK, BH), block 256 (8 warps). 32-row sub-tiles; phase-1 and
// phase-2 smem overlapped in a union to stay under 48 KB static.
// (unchanged from the passing round-5 version)
// ===========================================================================
union KvSmem {
    struct { float Xs[32][36]; float Wks[32][132]; float Wvs[32][132]; } p1;
    struct { float Kt[32][132]; float Vt[32][132]; } p2;
};

__global__ void __launch_bounds__(256) fused_kv_kernel(const float* __restrict__ x,
                                                       const float* __restrict__ Wk,
                                                       const float* __restrict__ Wv) {
    __shared__ KvSmem sm;

    const int chunk = blockIdx.x;
    const int bh    = blockIdx.y;
    const int b = bh / H_, h = bh % H_;

    const float* Wkh = Wk + (size_t)h * D_ * D_;
    const float* Wvh = Wv + (size_t)h * D_ * D_;
    const float* Xb  = x + (size_t)b * S_ * E_ + (size_t)h * D_;

    const int tid  = threadIdx.x;
    const int warp = tid >> 5;
    const int lane = tid & 31;
    const int wm1 = warp & 1;
    const int wn1 = warp >> 1;
    const int wm2 = warp & 3;
    const int wn2 = warp >> 2;

    CFrag acc_kv[2][4];
#pragma unroll
    for (int i = 0; i < 2; i++)
#pragma unroll
        for (int j = 0; j < 4; j++) wmma::fill_fragment(acc_kv[i][j], 0.f);

    float ksum_acc = 0.f;

    for (int sub = 0; sub < CHUNK_S_ / 32; sub++) {
        const int s0 = chunk * CHUNK_S_ + sub * 32;

        CFrag acck[2], accv[2];
#pragma unroll
        for (int j = 0; j < 2; j++) { wmma::fill_fragment(acck[j], 0.f); wmma::fill_fragment(accv[j], 0.f); }

        for (int k0 = 0; k0 < D_; k0 += 32) {
            {
                int r = tid >> 3, c4 = (tid & 7) * 4;
                *(float4*)&sm.p1.Xs[r][c4] = *(const float4*)&Xb[(size_t)(s0 + r) * E_ + k0 + c4];
            }
#pragma unroll
            for (int t = 0; t < 4; t++) {
                int f4i = tid + t * 256;
                int r = f4i >> 5, c4 = (f4i & 31) * 4;
                *(float4*)&sm.p1.Wks[r][c4] = *(const float4*)&Wkh[(size_t)(k0 + r) * D_ + c4];
                *(float4*)&sm.p1.Wvs[r][c4] = *(const float4*)&Wvh[(size_t)(k0 + r) * D_ + c4];
            }
            __syncthreads();
#pragma unroll
            for (int kk = 0; kk < 4; kk++) {
                AFrag a;
                wmma::load_matrix_sync(a, &sm.p1.Xs[wm1 * 16][kk * 8], 36);
                to_tf32(a);
#pragma unroll
                for (int j = 0; j < 2; j++) {
                    BFrag bfr;
                    wmma::load_matrix_sync(bfr, &sm.p1.Wks[kk * 8][wn1 * 32 + j * 16], 132);
                    to_tf32(bfr);
                    wmma::mma_sync(acck[j], a, bfr, acck[j]);
                    wmma::load_matrix_sync(bfr, &sm.p1.Wvs[kk * 8][wn1 * 32 + j * 16], 132);
                    to_tf32(bfr);
                    wmma::mma_sync(accv[j], a, bfr, accv[j]);
                }
            }
            __syncthreads();
        }
#pragma unroll
        for (int j = 0; j < 2; j++) {
#pragma unroll
            for (int e = 0; e < acck[j].num_elements; e++) acck[j].x[e] = phi_(acck[j].x[e]);
            wmma::store_matrix_sync(&sm.p2.Kt[wm1 * 16][wn1 * 32 + j * 16], acck[j], 132, wmma::mem_row_major);
            wmma::store_matrix_sync(&sm.p2.Vt[wm1 * 16][wn1 * 32 + j * 16], accv[j], 132, wmma::mem_row_major);
        }
        __syncthreads();

        if (warp < 4) {
            const int col = warp * 32 + lane;
#pragma unroll 8
            for (int r = 0; r < 32; r++) ksum_acc += sm.p2.Kt[r][col];
        }

#pragma unroll
        for (int kk = 0; kk < 4; kk++) {
            ATFrag a2[2];
#pragma unroll
            for (int i = 0; i < 2; i++) {
                wmma::load_matrix_sync(a2[i], &sm.p2.Kt[kk * 8][wm2 * 32 + i * 16], 132);
                to_tf32(a2[i]);
            }
#pragma unroll
            for (int j = 0; j < 4; j++) {
                BFrag bfr;
                wmma::load_matrix_sync(bfr, &sm.p2.Vt[kk * 8][wn2 * 64 + j * 16], 132);
                to_tf32(bfr);
#pragma unroll
                for (int i = 0; i < 2; i++) wmma::mma_sync(acc_kv[i][j], a2[i], bfr, acc_kv[i][j]);
            }
        }
        __syncthreads();
    }

    float* kvp = g_kvp + ((size_t)bh * NCHUNK_ + chunk) * D_ * D_;
#pragma unroll
    for (int i = 0; i < 2; i++)
#pragma unroll
        for (int j = 0; j < 4; j++)
            wmma::store_matrix_sync(&kvp[(size_t)(wm2 * 32 + i * 16) * D_ + wn2 * 64 + j * 16],
                                    acc_kv[i][j], D_, wmma::mem_row_major);
    if (warp < 4)
        g_ksp[((size_t)bh * NCHUNK_ + chunk) * D_ + warp * 32 + lane] = ksum_acc;
}

// ===========================================================================
// Kernel A2: reduce the NCHUNK partials.  grid = BH, block 256. (unchanged)
// ===========================================================================
__global__ void reduce_kernel() {
    const int bh = blockIdx.x;
    const int tid = threadIdx.x;
    const float* kvp = g_kvp + (size_t)bh * NCHUNK_ * D_ * D_;
    float* kv = g_kv + (size_t)bh * D_ * D_;
    for (int i = tid; i < D_ * D_; i += 256) {
        float s = 0.f;
#pragma unroll
        for (int c = 0; c < NCHUNK_; c++) s += kvp[(size_t)c * D_ * D_ + i];
        kv[i] = s;
    }
    if (tid < D_) {
        const float* ksp = g_ksp + (size_t)bh * NCHUNK_ * D_;
        float s = 0.f;
#pragma unroll
        for (int c = 0; c < NCHUNK_; c++) s += ksp[(size_t)c * D_ + tid];
        g_ks[(size_t)bh * D_ + tid] = s;
    }
}

// ===========================================================================
// Kernel B: fused Q-proj + phi + ctx (tf32 wmma).  grid = (S/32, BH), 256 thr.
// (unchanged from the passing round-5 version)
// ===========================================================================
__global__ void __launch_bounds__(256) fused_ctx_kernel(const float* __restrict__ x,
                                                        const float* __restrict__ Wq) {
    __shared__ float Xs[32][36];
    __shared__ float Ws[32][132];
    __shared__ float Qt[32][132];
    __shared__ float ksum_s[128];
    __shared__ float den_s[32];

    const int stile = blockIdx.x;
    const int bh    = blockIdx.y;
    const int b = bh / H_, h = bh % H_;

    const float* Wqh = Wq + (size_t)h * D_ * D_;
    const float* Xb  = x + (size_t)b * S_ * E_ + (size_t)h * D_;
    const float* kv  = g_kv + (size_t)bh * D_ * D_;

    const int tid  = threadIdx.x;
    const int warp = tid >> 5;
    const int wm = warp & 1;
    const int wn = warp >> 1;
    const int s0 = stile * 32;

    if (tid < 128) ksum_s[tid] = g_ks[(size_t)bh * D_ + tid];

    CFrag acc[2];
#pragma unroll
    for (int j = 0; j < 2; j++) wmma::fill_fragment(acc[j], 0.f);

    for (int k0 = 0; k0 < D_; k0 += 32) {
        {
            int r = tid >> 3, c4 = (tid & 7) * 4;
            *(float4*)&Xs[r][c4] = *(const float4*)&Xb[(size_t)(s0 + r) * E_ + k0 + c4];
        }
#pragma unroll
        for (int t = 0; t < 4; t++) {
            int f4i = tid + t * 256;
            int r = f4i >> 5, c4 = (f4i & 31) * 4;
            *(float4*)&Ws[r][c4] = *(const float4*)&Wqh[(size_t)(k0 + r) * D_ + c4];
        }
        __syncthreads();
#pragma unroll
        for (int kk = 0; kk < 4; kk++) {
            AFrag a;
            wmma::load_matrix_sync(a, &Xs[wm * 16][kk * 8], 36);
            to_tf32(a);
#pragma unroll
            for (int j = 0; j < 2; j++) {
                BFrag bfr;
                wmma::load_matrix_sync(bfr, &Ws[kk * 8][wn * 32 + j * 16], 132);
                to_tf32(bfr);
                wmma::mma_sync(acc[j], a, bfr, acc[j]);
            }
        }
        __syncthreads();
    }
#pragma unroll
    for (int j = 0; j < 2; j++) {
#pragma unroll
        for (int e = 0; e < acc[j].num_elements; e++) acc[j].x[e] = phi_(acc[j].x[e]);
        wmma::store_matrix_sync(&Qt[wm * 16][wn * 32 + j * 16], acc[j], 132, wmma::mem_row_major);
    }
    __syncthreads();

    if (tid < 32) {
        float dsum = 0.f;
#pragma unroll
        for (int c = 0; c < 128; c++) dsum = fmaf(Qt[tid][c], ksum_s[c], dsum);
        den_s[tid] = 1.f / (dsum + EPS_);
    }
    __syncthreads();
#pragma unroll
    for (int t = 0; t < 16; t++) {
        int i = tid + t * 256;
        int r = i >> 7, c = i & 127;
        Qt[r][c] *= den_s[r];
    }
    __syncthreads();

#pragma unroll
    for (int j = 0; j < 2; j++) wmma::fill_fragment(acc[j], 0.f);

    for (int k0 = 0; k0 < D_; k0 += 32) {
#pragma unroll
        for (int t = 0; t < 4; t++) {
            int f4i = tid + t * 256;
            int r = f4i >> 5, c4 = (f4i & 31) * 4;
            *(float4*)&Ws[r][c4] = *(const float4*)&kv[(size_t)(k0 + r) * D_ + c4];
        }
        __syncthreads();
#pragma unroll
        for (int kk = 0; kk < 4; kk++) {
            AFrag a;
            wmma::load_matrix_sync(a, &Qt[wm * 16][k0 + kk * 8], 132);
            to_tf32(a);
#pragma unroll
            for (int j = 0; j < 2; j++) {
                BFrag bfr;
                wmma::load_matrix_sync(bfr, &Ws[kk * 8][wn * 32 + j * 16], 132);
                to_tf32(bfr);
                wmma::mma_sync(acc[j], a, bfr, acc[j]);
            }
        }
        __syncthreads();
    }

    float* outp = g_comb + ((size_t)b * S_ + s0 + wm * 16) * E_ + h * D_ + wn * 32;
#pragma unroll
    for (int j = 0; j < 2; j++)
        wmma::store_matrix_sync(outp + j * 16, acc[j], E_, wmma::mem_row_major);
}

// ===========================================================================
// Kernel C v2: out = combined @ Wo + bo (tf32 wmma), cp.async double-buffered.
// grid = (E/128, B*S/128), block 256 (8 warps), 128x128 tile, k-step 16.
// smem: 2*(128*20 + 16*132)*4 + 16*132*4 = 45.8 KB static.
// ===========================================================================
#define OK_TK 16
#define OK_NIT (E_ / OK_TK)   // 128

__global__ void __launch_bounds__(256, 2) out_kernel(const float* __restrict__ Wo,
                                                     const float* __restrict__ bo,
                                                     float* __restrict__ out) {
    __shared__ __align__(16) float As[2][128][20];
    __shared__ __align__(16) float Bs[2][OK_TK][132];
    __shared__ __align__(16) float BiasS[16][132];

    const int col0 = blockIdx.x * 128;
    const int row0 = blockIdx.y * 128;
    const int tid  = threadIdx.x;
    const int warp = tid >> 5;
    const int wm = warp & 3;    // rows wm*32
    const int wn = warp >> 2;   // cols wn*64

    // A copy indices: 128x16 = 512 float4, 2 per thread
    const int ar0 = tid >> 2, ac0 = (tid & 3) * 4;           // t=0
    const int ar1 = (tid + 256) >> 2, ac1 = ac0;             // t=1 (same col pattern)
    // B copy indices: 16x128 = 512 float4, 2 per thread
    const int br0 = tid >> 5, bc0 = (tid & 31) * 4;
    const int br1 = (tid + 256) >> 5, bc1 = bc0;

    const float* Ag = g_comb + (size_t)row0 * E_;
    const float* Bg = Wo + (size_t)col0;

    // replicated bias tile -> init accumulators with bias
#pragma unroll
    for (int t = 0; t < 8; t++) {
        int i = tid + t * 256;
        int r = i >> 7, c = i & 127;
        BiasS[r][c] = bo[col0 + c];
    }
    __syncthreads();

    CFrag acc[2][4];
#pragma unroll
    for (int i = 0; i < 2; i++)
#pragma unroll
        for (int j = 0; j < 4; j++)
            wmma::load_matrix_sync(acc[i][j], &BiasS[0][wn * 64 + j * 16], 132, wmma::mem_row_major);
    __syncthreads();

    // ---- preload iter 0 into buffer 0 ----
    {
        const int k0 = 0;
        cpasync16(&As[0][ar0][ac0], &Ag[(size_t)ar0 * E_ + k0 + ac0]);
        cpasync16(&As[0][ar1][ac1], &Ag[(size_t)ar1 * E_ + k0 + ac1]);
        cpasync16(&Bs[0][br0][bc0], &Bg[(size_t)(k0 + br0) * E_ + bc0]);
        cpasync16(&Bs[0][br1][bc1], &Bg[(size_t)(k0 + br1) * E_ + bc1]);
    }
    CP_COMMIT();

    for (int it = 0; it < OK_NIT; it++) {
        const int cur = it & 1;
        if (it + 1 < OK_NIT) {
            const int nxt = cur ^ 1;
            const int k0 = (it + 1) * OK_TK;
            cpasync16(&As[nxt][ar0][ac0], &Ag[(size_t)ar0 * E_ + k0 + ac0]);
            cpasync16(&As[nxt][ar1][ac1], &Ag[(size_t)ar1 * E_ + k0 + ac1]);
            cpasync16(&Bs[nxt][br0][bc0], &Bg[(size_t)(k0 + br0) * E_ + bc0]);
            cpasync16(&Bs[nxt][br1][bc1], &Bg[(size_t)(k0 + br1) * E_ + bc1]);
        }
        CP_COMMIT();
        CP_WAIT(1);          // current buffer's group complete; newest may fly
        __syncthreads();

#pragma unroll
        for (int kk = 0; kk < OK_TK / 8; kk++) {
            AFrag a[2];
#pragma unroll
            for (int i = 0; i < 2; i++) {
                wmma::load_matrix_sync(a[i], &As[cur][wm * 32 + i * 16][kk * 8], 20);
                to_tf32(a[i]);
            }
#pragma unroll
            for (int j = 0; j < 4; j++) {
                BFrag bfr;
                wmma::load_matrix_sync(bfr, &Bs[cur][kk * 8][wn * 64 + j * 16], 132);
                to_tf32(bfr);
#pragma unroll
                for (int i = 0; i < 2; i++) wmma::mma_sync(acc[i][j], a[i], bfr, acc[i][j]);
            }
        }
        __syncthreads();     // done reading cur before it's overwritten at it+2
    }

#pragma unroll
    for (int i = 0; i < 2; i++)
#pragma unroll
        for (int j = 0; j < 4; j++)
            wmma::store_matrix_sync(out + (size_t)(row0 + wm * 32 + i * 16) * E_ + col0 + wn * 64 + j * 16,
                                    acc[i][j], E_, wmma::mem_row_major);
}

// ===========================================================================
extern "C" void kernel_launch(void* const* d_in, const int* in_sizes, int n_in,
                              void* d_out, int out_size) {
    const float* x  = (const float*)d_in[0];
    const float* Wq = (const float*)d_in[1];
    const float* Wk = (const float*)d_in[2];
    const float* Wv = (const float*)d_in[3];
    const float* Wo = (const float*)d_in[4];
    const float* bo = (const float*)d_in[5];
    float* out = (float*)d_out;

    fused_kv_kernel<<<dim3(NCHUNK_, BH_), 256>>>(x, Wk, Wv);
    reduce_kernel<<<BH_, 256>>>();
    fused_ctx_kernel<<<dim3(S_ / 32, BH_), 256>>>(x, Wq);
    out_kernel<<<dim3(E_ / 128, (B_ * S_) / 128), 256>>>(Wo, bo, out);
}

// round 8
// speedup vs baseline: 1.8807x; 1.0201x over previous
#include <cuda_runtime.h>
#include <mma.h>
#include <cstdint>

using namespace nvcuda;

#define B_  8
#define S_  2048
#define E_  2048
#define H_  16
#define D_  128
#define BH_ (B_ * H_)
#define NCHUNK_ 4
#define CHUNK_S_ (S_ / NCHUNK_)   // 512
#define EPS_ 1e-6f

typedef wmma::fragment<wmma::matrix_a, 16, 16, 8, wmma::precision::tf32, wmma::row_major> AFrag;
typedef wmma::fragment<wmma::matrix_a, 16, 16, 8, wmma::precision::tf32, wmma::col_major> ATFrag;
typedef wmma::fragment<wmma::matrix_b, 16, 16, 8, wmma::precision::tf32, wmma::row_major> BFrag;
typedef wmma::fragment<wmma::accumulator, 16, 16, 8, float> CFrag;

template <typename F>
__device__ __forceinline__ void to_tf32(F& f) {
#pragma unroll
    for (int i = 0; i < f.num_elements; i++) f.x[i] = wmma::__float_to_tf32(f.x[i]);
}

__device__ __forceinline__ float phi_(float y) { return (y > 0.f) ? (y + 1.f) : expf(y); }
__device__ __forceinline__ float rtf32_(float y) { return wmma::__float_to_tf32(y); }

__device__ __forceinline__ void cpasync16(void* smem, const void* gmem) {
    uint32_t s = (uint32_t)__cvta_generic_to_shared(smem);
    asm volatile("cp.async.cg.shared.global [%0], [%1], 16;" :: "r"(s), "l"(gmem));
}
#define CP_COMMIT()  asm volatile("cp.async.commit_group;")
#define CP_WAIT(N)   asm volatile("cp.async.wait_group %0;" :: "n"(N))

// ---------------- scratch (__device__ globals; no allocation allowed) ----------------
__device__ float g_kvp[(size_t)BH_ * NCHUNK_ * D_ * D_];   // 32 MB
__device__ float g_ksp[(size_t)BH_ * NCHUNK_ * D_];
__device__ float g_kv [(size_t)BH_ * D_ * D_];             // 8 MB (tf32-rounded)
__device__ float g_ks [(size_t)BH_ * D_];
__device__ float g_comb[(size_t)B_ * S_ * E_];             // 128 MB (tf32-rounded at store)
__device__ float g_wor[(size_t)E_ * E_];                   // 16 MB pre-rounded Wo

// ===========================================================================
// Prep: round Wo -> tf32 into g_wor.  grid-stride float4.
// ===========================================================================
__global__ void round_wo_kernel(const float4* __restrict__ src) {
    float4* dst = (float4*)g_wor;
    const int n4 = (E_ * E_) / 4;
    int i = blockIdx.x * blockDim.x + threadIdx.x;
    int stride = gridDim.x * blockDim.x;
    for (; i < n4; i += stride) {
        float4 v = src[i];
        v.x = rtf32_(v.x); v.y = rtf32_(v.y); v.z = rtf32_(v.z); v.w = rtf32_(v.w);
        dst[i] = v;
    }
}

// ===========================================================================
// Kernel A: fused K-proj, V-proj, phi, partial kv & ksum (tf32 wmma).
// grid = (NCHUNK, BH), block 256 (8 warps). Phase-1 fragments converted at
// load (x/W unrounded); Kt/Vt rounded at smem store so phase-2 (kv GEMM)
// has no in-loop conversions.
// ===========================================================================
union KvSmem {
    struct { float Xs[32][36]; float Wks[32][132]; float Wvs[32][132]; } p1;
    struct { float Kt[32][132]; float Vt[32][132]; } p2;
};

__global__ void __launch_bounds__(256) fused_kv_kernel(const float* __restrict__ x,
                                                       const float* __restrict__ Wk,
                                                       const float* __restrict__ Wv) {
    __shared__ KvSmem sm;

    const int chunk = blockIdx.x;
    const int bh    = blockIdx.y;
    const int b = bh / H_, h = bh % H_;

    const float* Wkh = Wk + (size_t)h * D_ * D_;
    const float* Wvh = Wv + (size_t)h * D_ * D_;
    const float* Xb  = x + (size_t)b * S_ * E_ + (size_t)h * D_;

    const int tid  = threadIdx.x;
    const int warp = tid >> 5;
    const int lane = tid & 31;
    const int wm1 = warp & 1;
    const int wn1 = warp >> 1;
    const int wm2 = warp & 3;
    const int wn2 = warp >> 2;

    CFrag acc_kv[2][4];
#pragma unroll
    for (int i = 0; i < 2; i++)
#pragma unroll
        for (int j = 0; j < 4; j++) wmma::fill_fragment(acc_kv[i][j], 0.f);

    float ksum_acc = 0.f;

    for (int sub = 0; sub < CHUNK_S_ / 32; sub++) {
        const int s0 = chunk * CHUNK_S_ + sub * 32;

        CFrag acck[2], accv[2];
#pragma unroll
        for (int j = 0; j < 2; j++) { wmma::fill_fragment(acck[j], 0.f); wmma::fill_fragment(accv[j], 0.f); }

        for (int k0 = 0; k0 < D_; k0 += 32) {
            {
                int r = tid >> 3, c4 = (tid & 7) * 4;
                *(float4*)&sm.p1.Xs[r][c4] = *(const float4*)&Xb[(size_t)(s0 + r) * E_ + k0 + c4];
            }
#pragma unroll
            for (int t = 0; t < 4; t++) {
                int f4i = tid + t * 256;
                int r = f4i >> 5, c4 = (f4i & 31) * 4;
                *(float4*)&sm.p1.Wks[r][c4] = *(const float4*)&Wkh[(size_t)(k0 + r) * D_ + c4];
                *(float4*)&sm.p1.Wvs[r][c4] = *(const float4*)&Wvh[(size_t)(k0 + r) * D_ + c4];
            }
            __syncthreads();
#pragma unroll
            for (int kk = 0; kk < 4; kk++) {
                AFrag a;
                wmma::load_matrix_sync(a, &sm.p1.Xs[wm1 * 16][kk * 8], 36);
                to_tf32(a);
#pragma unroll
                for (int j = 0; j < 2; j++) {
                    BFrag bfr;
                    wmma::load_matrix_sync(bfr, &sm.p1.Wks[kk * 8][wn1 * 32 + j * 16], 132);
                    to_tf32(bfr);
                    wmma::mma_sync(acck[j], a, bfr, acck[j]);
                    wmma::load_matrix_sync(bfr, &sm.p1.Wvs[kk * 8][wn1 * 32 + j * 16], 132);
                    to_tf32(bfr);
                    wmma::mma_sync(accv[j], a, bfr, accv[j]);
                }
            }
            __syncthreads();
        }
        // round phi(K), V at smem store: phase-2 operands pre-rounded
#pragma unroll
        for (int j = 0; j < 2; j++) {
#pragma unroll
            for (int e = 0; e < acck[j].num_elements; e++) acck[j].x[e] = rtf32_(phi_(acck[j].x[e]));
#pragma unroll
            for (int e = 0; e < accv[j].num_elements; e++) accv[j].x[e] = rtf32_(accv[j].x[e]);
            wmma::store_matrix_sync(&sm.p2.Kt[wm1 * 16][wn1 * 32 + j * 16], acck[j], 132, wmma::mem_row_major);
            wmma::store_matrix_sync(&sm.p2.Vt[wm1 * 16][wn1 * 32 + j * 16], accv[j], 132, wmma::mem_row_major);
        }
        __syncthreads();

        if (warp < 4) {
            const int col = warp * 32 + lane;
#pragma unroll 8
            for (int r = 0; r < 32; r++) ksum_acc += sm.p2.Kt[r][col];
        }

#pragma unroll
        for (int kk = 0; kk < 4; kk++) {
            ATFrag a2[2];
#pragma unroll
            for (int i = 0; i < 2; i++)
                wmma::load_matrix_sync(a2[i], &sm.p2.Kt[kk * 8][wm2 * 32 + i * 16], 132);
#pragma unroll
            for (int j = 0; j < 4; j++) {
                BFrag bfr;
                wmma::load_matrix_sync(bfr, &sm.p2.Vt[kk * 8][wn2 * 64 + j * 16], 132);
#pragma unroll
                for (int i = 0; i < 2; i++) wmma::mma_sync(acc_kv[i][j], a2[i], bfr, acc_kv[i][j]);
            }
        }
        __syncthreads();
    }

    float* kvp = g_kvp + ((size_t)bh * NCHUNK_ + chunk) * D_ * D_;
#pragma unroll
    for (int i = 0; i < 2; i++)
#pragma unroll
        for (int j = 0; j < 4; j++)
            wmma::store_matrix_sync(&kvp[(size_t)(wm2 * 32 + i * 16) * D_ + wn2 * 64 + j * 16],
                                    acc_kv[i][j], D_, wmma::mem_row_major);
    if (warp < 4)
        g_ksp[((size_t)bh * NCHUNK_ + chunk) * D_ + warp * 32 + lane] = ksum_acc;
}

// ===========================================================================
// Kernel A2: reduce the NCHUNK partials; round kv (B operand of ctx GEMM).
// ===========================================================================
__global__ void reduce_kernel() {
    const int bh = blockIdx.x;
    const int tid = threadIdx.x;
    const float* kvp = g_kvp + (size_t)bh * NCHUNK_ * D_ * D_;
    float* kv = g_kv + (size_t)bh * D_ * D_;
    for (int i = tid; i < D_ * D_; i += 256) {
        float s = 0.f;
#pragma unroll
        for (int c = 0; c < NCHUNK_; c++) s += kvp[(size_t)c * D_ * D_ + i];
        kv[i] = rtf32_(s);
    }
    if (tid < D_) {
        const float* ksp = g_ksp + (size_t)bh * NCHUNK_ * D_;
        float s = 0.f;
#pragma unroll
        for (int c = 0; c < NCHUNK_; c++) s += ksp[(size_t)c * D_ + tid];
        g_ks[(size_t)bh * D_ + tid] = s;
    }
}

// ===========================================================================
// Kernel B: fused Q-proj + phi + ctx (tf32 wmma).  grid = (S/32, BH), 256 thr.
// Phase-1 converts at load; Qt rounded at smem store, kv pre-rounded ->
// phase-2 (ctx GEMM) has no in-loop conversions. g_comb rounded at store.
// ===========================================================================
__global__ void __launch_bounds__(256) fused_ctx_kernel(const float* __restrict__ x,
                                                        const float* __restrict__ Wq) {
    __shared__ float Xs[32][36];
    __shared__ float Ws[32][132];
    __shared__ float Qt[32][132];
    __shared__ float ksum_s[128];
    __shared__ float den_s[32];

    const int stile = blockIdx.x;
    const int bh    = blockIdx.y;
    const int b = bh / H_, h = bh % H_;

    const float* Wqh = Wq + (size_t)h * D_ * D_;
    const float* Xb  = x + (size_t)b * S_ * E_ + (size_t)h * D_;
    const float* kv  = g_kv + (size_t)bh * D_ * D_;

    const int tid  = threadIdx.x;
    const int warp = tid >> 5;
    const int wm = warp & 1;
    const int wn = warp >> 1;
    const int s0 = stile * 32;

    if (tid < 128) ksum_s[tid] = g_ks[(size_t)bh * D_ + tid];

    CFrag acc[2];
#pragma unroll
    for (int j = 0; j < 2; j++) wmma::fill_fragment(acc[j], 0.f);

    for (int k0 = 0; k0 < D_; k0 += 32) {
        {
            int r = tid >> 3, c4 = (tid & 7) * 4;
            *(float4*)&Xs[r][c4] = *(const float4*)&Xb[(size_t)(s0 + r) * E_ + k0 + c4];
        }
#pragma unroll
        for (int t = 0; t < 4; t++) {
            int f4i = tid + t * 256;
            int r = f4i >> 5, c4 = (f4i & 31) * 4;
            *(float4*)&Ws[r][c4] = *(const float4*)&Wqh[(size_t)(k0 + r) * D_ + c4];
        }
        __syncthreads();
#pragma unroll
        for (int kk = 0; kk < 4; kk++) {
            AFrag a;
            wmma::load_matrix_sync(a, &Xs[wm * 16][kk * 8], 36);
            to_tf32(a);
#pragma unroll
            for (int j = 0; j < 2; j++) {
                BFrag bfr;
                wmma::load_matrix_sync(bfr, &Ws[kk * 8][wn * 32 + j * 16], 132);
                to_tf32(bfr);
                wmma::mma_sync(acc[j], a, bfr, acc[j]);
            }
        }
        __syncthreads();
    }
#pragma unroll
    for (int j = 0; j < 2; j++) {
#pragma unroll
        for (int e = 0; e < acc[j].num_elements; e++) acc[j].x[e] = rtf32_(phi_(acc[j].x[e]));
        wmma::store_matrix_sync(&Qt[wm * 16][wn * 32 + j * 16], acc[j], 132, wmma::mem_row_major);
    }
    __syncthreads();

    if (tid < 32) {
        float dsum = 0.f;
#pragma unroll
        for (int c = 0; c < 128; c++) dsum = fmaf(Qt[tid][c], ksum_s[c], dsum);
        den_s[tid] = 1.f / (dsum + EPS_);
    }
    __syncthreads();
#pragma unroll
    for (int t = 0; t < 16; t++) {
        int i = tid + t * 256;
        int r = i >> 7, c = i & 127;
        Qt[r][c] = rtf32_(Qt[r][c] * den_s[r]);
    }
    __syncthreads();

#pragma unroll
    for (int j = 0; j < 2; j++) wmma::fill_fragment(acc[j], 0.f);

    for (int k0 = 0; k0 < D_; k0 += 32) {
#pragma unroll
        for (int t = 0; t < 4; t++) {
            int f4i = tid + t * 256;
            int r = f4i >> 5, c4 = (f4i & 31) * 4;
            *(float4*)&Ws[r][c4] = *(const float4*)&kv[(size_t)(k0 + r) * D_ + c4];
        }
        __syncthreads();
#pragma unroll
        for (int kk = 0; kk < 4; kk++) {
            AFrag a;
            wmma::load_matrix_sync(a, &Qt[wm * 16][k0 + kk * 8], 132);
#pragma unroll
            for (int j = 0; j < 2; j++) {
                BFrag bfr;
                wmma::load_matrix_sync(bfr, &Ws[kk * 8][wn * 32 + j * 16], 132);
                wmma::mma_sync(acc[j], a, bfr, acc[j]);
            }
        }
        __syncthreads();
    }

    // round ctx at store: it is the A operand of the output GEMM
    float* outp = g_comb + ((size_t)b * S_ + s0 + wm * 16) * E_ + h * D_ + wn * 32;
#pragma unroll
    for (int j = 0; j < 2; j++) {
#pragma unroll
        for (int e = 0; e < acc[j].num_elements; e++) acc[j].x[e] = rtf32_(acc[j].x[e]);
        wmma::store_matrix_sync(outp + j * 16, acc[j], E_, wmma::mem_row_major);
    }
}

// ===========================================================================
// Kernel C: out = g_comb(rounded) @ g_wor(rounded) + bo — NO in-loop
// conversions.  cp.async double-buffered, 128x128 tile, k-step 16.
// ===========================================================================
#define OK_TK 16
#define OK_NIT (E_ / OK_TK)   // 128

__global__ void __launch_bounds__(256, 2) out_kernel(const float* __restrict__ bo,
                                                     float* __restrict__ out) {
    __shared__ __align__(16) float As[2][128][20];
    __shared__ __align__(16) float Bs[2][OK_TK][132];
    __shared__ __align__(16) float BiasS[16][132];

    const int col0 = blockIdx.x * 128;
    const int row0 = blockIdx.y * 128;
    const int tid  = threadIdx.x;
    const int warp = tid >> 5;
    const int wm = warp & 3;    // rows wm*32
    const int wn = warp >> 2;   // cols wn*64

    const int ar0 = tid >> 2, ac0 = (tid & 3) * 4;
    const int ar1 = (tid + 256) >> 2, ac1 = ac0;
    const int br0 = tid >> 5, bc0 = (tid & 31) * 4;
    const int br1 = (tid + 256) >> 5, bc1 = bc0;

    const float* Ag = g_comb + (size_t)row0 * E_;
    const float* Bg = g_wor + (size_t)col0;

#pragma unroll
    for (int t = 0; t < 8; t++) {
        int i = tid + t * 256;
        int r = i >> 7, c = i & 127;
        BiasS[r][c] = bo[col0 + c];
    }
    __syncthreads();

    CFrag acc[2][4];
#pragma unroll
    for (int i = 0; i < 2; i++)
#pragma unroll
        for (int j = 0; j < 4; j++)
            wmma::load_matrix_sync(acc[i][j], &BiasS[0][wn * 64 + j * 16], 132, wmma::mem_row_major);
    __syncthreads();

    {
        const int k0 = 0;
        cpasync16(&As[0][ar0][ac0], &Ag[(size_t)ar0 * E_ + k0 + ac0]);
        cpasync16(&As[0][ar1][ac1], &Ag[(size_t)ar1 * E_ + k0 + ac1]);
        cpasync16(&Bs[0][br0][bc0], &Bg[(size_t)(k0 + br0) * E_ + bc0]);
        cpasync16(&Bs[0][br1][bc1], &Bg[(size_t)(k0 + br1) * E_ + bc1]);
    }
    CP_COMMIT();

    for (int it = 0; it < OK_NIT; it++) {
        const int cur = it & 1;
        if (it + 1 < OK_NIT) {
            const int nxt = cur ^ 1;
            const int k0 = (it + 1) * OK_TK;
            cpasync16(&As[nxt][ar0][ac0], &Ag[(size_t)ar0 * E_ + k0 + ac0]);
            cpasync16(&As[nxt][ar1][ac1], &Ag[(size_t)ar1 * E_ + k0 + ac1]);
            cpasync16(&Bs[nxt][br0][bc0], &Bg[(size_t)(k0 + br0) * E_ + bc0]);
            cpasync16(&Bs[nxt][br1][bc1], &Bg[(size_t)(k0 + br1) * E_ + bc1]);
        }
        CP_COMMIT();
        CP_WAIT(1);
        __syncthreads();

#pragma unroll
        for (int kk = 0; kk < OK_TK / 8; kk++) {
            AFrag a[2];
#pragma unroll
            for (int i = 0; i < 2; i++)
                wmma::load_matrix_sync(a[i], &As[cur][wm * 32 + i * 16][kk * 8], 20);
#pragma unroll
            for (int j = 0; j < 4; j++) {
                BFrag bfr;
                wmma::load_matrix_sync(bfr, &Bs[cur][kk * 8][wn * 64 + j * 16], 132);
#pragma unroll
                for (int i = 0; i < 2; i++) wmma::mma_sync(acc[i][j], a[i], bfr, acc[i][j]);
            }
        }
        __syncthreads();
    }

#pragma unroll
    for (int i = 0; i < 2; i++)
#pragma unroll
        for (int j = 0; j < 4; j++)
            wmma::store_matrix_sync(out + (size_t)(row0 + wm * 32 + i * 16) * E_ + col0 + wn * 64 + j * 16,
                                    acc[i][j], E_, wmma::mem_row_major);
}

// ===========================================================================
extern "C" void kernel_launch(void* const* d_in, const int* in_sizes, int n_in,
                              void* d_out, int out_size) {
    const float* x  = (const float*)d_in[0];
    const float* Wq = (const float*)d_in[1];
    const float* Wk = (const float*)d_in[2];
    const float* Wv = (const float*)d_in[3];
    const float* Wo = (const float*)d_in[4];
    const float* bo = (const float*)d_in[5];
    float* out = (float*)d_out;

    round_wo_kernel<<<1024, 256>>>((const float4*)Wo);
    fused_kv_kernel<<<dim3(NCHUNK_, BH_), 256>>>(x, Wk, Wv);
    reduce_kernel<<<BH_, 256>>>();
    fused_ctx_kernel<<<dim3(S_ / 32, BH_), 256>>>(x, Wq);
    out_kernel<<<dim3(E_ / 128, (B_ * S_) / 128), 256>>>(bo, out);
}

// round 9
// speedup vs baseline: 3.5910x; 1.9094x over previous
#include <cuda_runtime.h>
#include <mma.h>
#include <cuda_fp16.h>
#include <cstdint>

using namespace nvcuda;

#define B_  8
#define S_  2048
#define E_  2048
#define H_  16
#define D_  128
#define BH_ (B_ * H_)
#define NCHUNK_ 4
#define CHUNK_S_ (S_ / NCHUNK_)   // 512
#define EPS_ 1e-6f

typedef wmma::fragment<wmma::matrix_a, 16, 16, 8, wmma::precision::tf32, wmma::row_major> AFrag;
typedef wmma::fragment<wmma::matrix_a, 16, 16, 8, wmma::precision::tf32, wmma::col_major> ATFrag;
typedef wmma::fragment<wmma::matrix_b, 16, 16, 8, wmma::precision::tf32, wmma::row_major> BFrag;
typedef wmma::fragment<wmma::accumulator, 16, 16, 8, float> CFrag;

typedef wmma::fragment<wmma::matrix_a, 16, 16, 16, __half, wmma::row_major> AFragH;
typedef wmma::fragment<wmma::matrix_b, 16, 16, 16, __half, wmma::row_major> BFragH;
typedef wmma::fragment<wmma::accumulator, 16, 16, 16, float> CFragH;

template <typename F>
__device__ __forceinline__ void to_tf32(F& f) {
#pragma unroll
    for (int i = 0; i < f.num_elements; i++) f.x[i] = wmma::__float_to_tf32(f.x[i]);
}

__device__ __forceinline__ float phi_(float y) { return (y > 0.f) ? (y + 1.f) : expf(y); }
__device__ __forceinline__ float rtf32_(float y) { return wmma::__float_to_tf32(y); }

__device__ __forceinline__ void cpasync16(void* smem, const void* gmem) {
    uint32_t s = (uint32_t)__cvta_generic_to_shared(smem);
    asm volatile("cp.async.cg.shared.global [%0], [%1], 16;" :: "r"(s), "l"(gmem));
}
#define CP_COMMIT()  asm volatile("cp.async.commit_group;")
#define CP_WAIT(N)   asm volatile("cp.async.wait_group %0;" :: "n"(N))

// ---------------- scratch (__device__ globals; no allocation allowed) ----------------
__device__ float  g_kvp[(size_t)BH_ * NCHUNK_ * D_ * D_];   // 32 MB
__device__ float  g_ksp[(size_t)BH_ * NCHUNK_ * D_];
__device__ float  g_kv [(size_t)BH_ * D_ * D_];             // 8 MB (tf32-rounded)
__device__ float  g_ks [(size_t)BH_ * D_];
__device__ __half g_combh[(size_t)B_ * S_ * E_];            // 64 MB (fp16 combined heads)
__device__ __half g_woh [(size_t)E_ * E_];                  // 8 MB fp16 Wo

// ===========================================================================
// Prep: convert Wo -> fp16.  grid-stride float4 -> 2x half2.
// ===========================================================================
__global__ void wo_half_kernel(const float4* __restrict__ src) {
    const int n4 = (E_ * E_) / 4;
    int i = blockIdx.x * blockDim.x + threadIdx.x;
    int stride = gridDim.x * blockDim.x;
    for (; i < n4; i += stride) {
        float4 v = src[i];
        __half2* d = (__half2*)&g_woh[(size_t)i * 4];
        d[0] = __floats2half2_rn(v.x, v.y);
        d[1] = __floats2half2_rn(v.z, v.w);
    }
}

// ===========================================================================
// Kernel A: fused K-proj, V-proj, phi, partial kv & ksum (tf32 wmma).
// (unchanged from passing round 8)
// ===========================================================================
union KvSmem {
    struct { float Xs[32][36]; float Wks[32][132]; float Wvs[32][132]; } p1;
    struct { float Kt[32][132]; float Vt[32][132]; } p2;
};

__global__ void __launch_bounds__(256) fused_kv_kernel(const float* __restrict__ x,
                                                       const float* __restrict__ Wk,
                                                       const float* __restrict__ Wv) {
    __shared__ KvSmem sm;

    const int chunk = blockIdx.x;
    const int bh    = blockIdx.y;
    const int b = bh / H_, h = bh % H_;

    const float* Wkh = Wk + (size_t)h * D_ * D_;
    const float* Wvh = Wv + (size_t)h * D_ * D_;
    const float* Xb  = x + (size_t)b * S_ * E_ + (size_t)h * D_;

    const int tid  = threadIdx.x;
    const int warp = tid >> 5;
    const int lane = tid & 31;
    const int wm1 = warp & 1;
    const int wn1 = warp >> 1;
    const int wm2 = warp & 3;
    const int wn2 = warp >> 2;

    CFrag acc_kv[2][4];
#pragma unroll
    for (int i = 0; i < 2; i++)
#pragma unroll
        for (int j = 0; j < 4; j++) wmma::fill_fragment(acc_kv[i][j], 0.f);

    float ksum_acc = 0.f;

    for (int sub = 0; sub < CHUNK_S_ / 32; sub++) {
        const int s0 = chunk * CHUNK_S_ + sub * 32;

        CFrag acck[2], accv[2];
#pragma unroll
        for (int j = 0; j < 2; j++) { wmma::fill_fragment(acck[j], 0.f); wmma::fill_fragment(accv[j], 0.f); }

        for (int k0 = 0; k0 < D_; k0 += 32) {
            {
                int r = tid >> 3, c4 = (tid & 7) * 4;
                *(float4*)&sm.p1.Xs[r][c4] = *(const float4*)&Xb[(size_t)(s0 + r) * E_ + k0 + c4];
            }
#pragma unroll
            for (int t = 0; t < 4; t++) {
                int f4i = tid + t * 256;
                int r = f4i >> 5, c4 = (f4i & 31) * 4;
                *(float4*)&sm.p1.Wks[r][c4] = *(const float4*)&Wkh[(size_t)(k0 + r) * D_ + c4];
                *(float4*)&sm.p1.Wvs[r][c4] = *(const float4*)&Wvh[(size_t)(k0 + r) * D_ + c4];
            }
            __syncthreads();
#pragma unroll
            for (int kk = 0; kk < 4; kk++) {
                AFrag a;
                wmma::load_matrix_sync(a, &sm.p1.Xs[wm1 * 16][kk * 8], 36);
                to_tf32(a);
#pragma unroll
                for (int j = 0; j < 2; j++) {
                    BFrag bfr;
                    wmma::load_matrix_sync(bfr, &sm.p1.Wks[kk * 8][wn1 * 32 + j * 16], 132);
                    to_tf32(bfr);
                    wmma::mma_sync(acck[j], a, bfr, acck[j]);
                    wmma::load_matrix_sync(bfr, &sm.p1.Wvs[kk * 8][wn1 * 32 + j * 16], 132);
                    to_tf32(bfr);
                    wmma::mma_sync(accv[j], a, bfr, accv[j]);
                }
            }
            __syncthreads();
        }
#pragma unroll
        for (int j = 0; j < 2; j++) {
#pragma unroll
            for (int e = 0; e < acck[j].num_elements; e++) acck[j].x[e] = rtf32_(phi_(acck[j].x[e]));
#pragma unroll
            for (int e = 0; e < accv[j].num_elements; e++) accv[j].x[e] = rtf32_(accv[j].x[e]);
            wmma::store_matrix_sync(&sm.p2.Kt[wm1 * 16][wn1 * 32 + j * 16], acck[j], 132, wmma::mem_row_major);
            wmma::store_matrix_sync(&sm.p2.Vt[wm1 * 16][wn1 * 32 + j * 16], accv[j], 132, wmma::mem_row_major);
        }
        __syncthreads();

        if (warp < 4) {
            const int col = warp * 32 + lane;
#pragma unroll 8
            for (int r = 0; r < 32; r++) ksum_acc += sm.p2.Kt[r][col];
        }

#pragma unroll
        for (int kk = 0; kk < 4; kk++) {
            ATFrag a2[2];
#pragma unroll
            for (int i = 0; i < 2; i++)
                wmma::load_matrix_sync(a2[i], &sm.p2.Kt[kk * 8][wm2 * 32 + i * 16], 132);
#pragma unroll
            for (int j = 0; j < 4; j++) {
                BFrag bfr;
                wmma::load_matrix_sync(bfr, &sm.p2.Vt[kk * 8][wn2 * 64 + j * 16], 132);
#pragma unroll
                for (int i = 0; i < 2; i++) wmma::mma_sync(acc_kv[i][j], a2[i], bfr, acc_kv[i][j]);
            }
        }
        __syncthreads();
    }

    float* kvp = g_kvp + ((size_t)bh * NCHUNK_ + chunk) * D_ * D_;
#pragma unroll
    for (int i = 0; i < 2; i++)
#pragma unroll
        for (int j = 0; j < 4; j++)
            wmma::store_matrix_sync(&kvp[(size_t)(wm2 * 32 + i * 16) * D_ + wn2 * 64 + j * 16],
                                    acc_kv[i][j], D_, wmma::mem_row_major);
    if (warp < 4)
        g_ksp[((size_t)bh * NCHUNK_ + chunk) * D_ + warp * 32 + lane] = ksum_acc;
}

// ===========================================================================
// Kernel A2: reduce the NCHUNK partials; round kv (B operand of ctx GEMM).
// ===========================================================================
__global__ void reduce_kernel() {
    const int bh = blockIdx.x;
    const int tid = threadIdx.x;
    const float* kvp = g_kvp + (size_t)bh * NCHUNK_ * D_ * D_;
    float* kv = g_kv + (size_t)bh * D_ * D_;
    for (int i = tid; i < D_ * D_; i += 256) {
        float s = 0.f;
#pragma unroll
        for (int c = 0; c < NCHUNK_; c++) s += kvp[(size_t)c * D_ * D_ + i];
        kv[i] = rtf32_(s);
    }
    if (tid < D_) {
        const float* ksp = g_ksp + (size_t)bh * NCHUNK_ * D_;
        float s = 0.f;
#pragma unroll
        for (int c = 0; c < NCHUNK_; c++) s += ksp[(size_t)c * D_ + tid];
        g_ks[(size_t)bh * D_ + tid] = s;
    }
}

// ===========================================================================
// Kernel B: fused Q-proj + phi + ctx (tf32 wmma).  grid = (S/32, BH), 256 thr.
// Epilogue now stages the ctx tile in smem and writes fp16 g_combh.
// ===========================================================================
__global__ void __launch_bounds__(256) fused_ctx_kernel(const float* __restrict__ x,
                                                        const float* __restrict__ Wq) {
    __shared__ float Xs[32][36];
    __shared__ float Ws[32][132];
    __shared__ float Qt[32][132];
    __shared__ float ksum_s[128];
    __shared__ float den_s[32];

    const int stile = blockIdx.x;
    const int bh    = blockIdx.y;
    const int b = bh / H_, h = bh % H_;

    const float* Wqh = Wq + (size_t)h * D_ * D_;
    const float* Xb  = x + (size_t)b * S_ * E_ + (size_t)h * D_;
    const float* kv  = g_kv + (size_t)bh * D_ * D_;

    const int tid  = threadIdx.x;
    const int warp = tid >> 5;
    const int wm = warp & 1;
    const int wn = warp >> 1;
    const int s0 = stile * 32;

    if (tid < 128) ksum_s[tid] = g_ks[(size_t)bh * D_ + tid];

    CFrag acc[2];
#pragma unroll
    for (int j = 0; j < 2; j++) wmma::fill_fragment(acc[j], 0.f);

    for (int k0 = 0; k0 < D_; k0 += 32) {
        {
            int r = tid >> 3, c4 = (tid & 7) * 4;
            *(float4*)&Xs[r][c4] = *(const float4*)&Xb[(size_t)(s0 + r) * E_ + k0 + c4];
        }
#pragma unroll
        for (int t = 0; t < 4; t++) {
            int f4i = tid + t * 256;
            int r = f4i >> 5, c4 = (f4i & 31) * 4;
            *(float4*)&Ws[r][c4] = *(const float4*)&Wqh[(size_t)(k0 + r) * D_ + c4];
        }
        __syncthreads();
#pragma unroll
        for (int kk = 0; kk < 4; kk++) {
            AFrag a;
            wmma::load_matrix_sync(a, &Xs[wm * 16][kk * 8], 36);
            to_tf32(a);
#pragma unroll
            for (int j = 0; j < 2; j++) {
                BFrag bfr;
                wmma::load_matrix_sync(bfr, &Ws[kk * 8][wn * 32 + j * 16], 132);
                to_tf32(bfr);
                wmma::mma_sync(acc[j], a, bfr, acc[j]);
            }
        }
        __syncthreads();
    }
#pragma unroll
    for (int j = 0; j < 2; j++) {
#pragma unroll
        for (int e = 0; e < acc[j].num_elements; e++) acc[j].x[e] = rtf32_(phi_(acc[j].x[e]));
        wmma::store_matrix_sync(&Qt[wm * 16][wn * 32 + j * 16], acc[j], 132, wmma::mem_row_major);
    }
    __syncthreads();

    if (tid < 32) {
        float dsum = 0.f;
#pragma unroll
        for (int c = 0; c < 128; c++) dsum = fmaf(Qt[tid][c], ksum_s[c], dsum);
        den_s[tid] = 1.f / (dsum + EPS_);
    }
    __syncthreads();
#pragma unroll
    for (int t = 0; t < 16; t++) {
        int i = tid + t * 256;
        int r = i >> 7, c = i & 127;
        Qt[r][c] = rtf32_(Qt[r][c] * den_s[r]);
    }
    __syncthreads();

#pragma unroll
    for (int j = 0; j < 2; j++) wmma::fill_fragment(acc[j], 0.f);

    for (int k0 = 0; k0 < D_; k0 += 32) {
#pragma unroll
        for (int t = 0; t < 4; t++) {
            int f4i = tid + t * 256;
            int r = f4i >> 5, c4 = (f4i & 31) * 4;
            *(float4*)&Ws[r][c4] = *(const float4*)&kv[(size_t)(k0 + r) * D_ + c4];
        }
        __syncthreads();
#pragma unroll
        for (int kk = 0; kk < 4; kk++) {
            AFrag a;
            wmma::load_matrix_sync(a, &Qt[wm * 16][k0 + kk * 8], 132);
#pragma unroll
            for (int j = 0; j < 2; j++) {
                BFrag bfr;
                wmma::load_matrix_sync(bfr, &Ws[kk * 8][wn * 32 + j * 16], 132);
                wmma::mma_sync(acc[j], a, bfr, acc[j]);
            }
        }
        __syncthreads();
    }

    // stage ctx tile (32x128) in Ws, then write fp16 to g_combh coalesced
#pragma unroll
    for (int j = 0; j < 2; j++)
        wmma::store_matrix_sync(&Ws[wm * 16][wn * 32 + j * 16], acc[j], 132, wmma::mem_row_major);
    __syncthreads();
#pragma unroll
    for (int t = 0; t < 8; t++) {
        int i = tid + t * 256;            // 0..2047 -> 32 rows x 64 half2
        int r = i >> 6, c2 = i & 63;
        __half2 v = __floats2half2_rn(Ws[r][c2 * 2], Ws[r][c2 * 2 + 1]);
        *(__half2*)&g_combh[((size_t)(b * S_ + s0 + r)) * E_ + h * D_ + c2 * 2] = v;
    }
}

// ===========================================================================
// Kernel C: out = g_combh @ g_woh + bo (fp16 wmma m16n16k16, fp32 accum).
// cp.async double-buffered, 128x128 tile, k-step 32.
// smem: A 2*128*40*2 + B 2*32*136*2 + bias 16*132*4 = 46.3 KB static.
// ===========================================================================
#define OKH_TK 32
#define OKH_NIT (E_ / OKH_TK)   // 64

__global__ void __launch_bounds__(256, 2) out_kernel(const float* __restrict__ bo,
                                                     float* __restrict__ out) {
    __shared__ __align__(16) __half Ah[2][128][40];
    __shared__ __align__(16) __half Bh[2][OKH_TK][136];
    __shared__ __align__(16) float BiasS[16][132];

    const int col0 = blockIdx.x * 128;
    const int row0 = blockIdx.y * 128;
    const int tid  = threadIdx.x;
    const int warp = tid >> 5;
    const int wm = warp & 3;    // rows wm*32
    const int wn = warp >> 2;   // cols wn*64

    // A tile 128x32 half = 512 x 16B segments (4 per row); B tile 32x128 half = 512 (16 per row)
    const int ar0 = tid >> 2,         ac0 = (tid & 3) * 8;
    const int ar1 = (tid + 256) >> 2, ac1 = ac0;
    const int br0 = tid >> 4,         bc0 = (tid & 15) * 8;
    const int br1 = (tid + 256) >> 4, bc1 = bc0;

    const __half* Ag = g_combh + (size_t)row0 * E_;
    const __half* Bg = g_woh + (size_t)col0;

#pragma unroll
    for (int t = 0; t < 8; t++) {
        int i = tid + t * 256;
        int r = i >> 7, c = i & 127;
        BiasS[r][c] = bo[col0 + c];
    }
    __syncthreads();

    CFragH acc[2][4];
#pragma unroll
    for (int i = 0; i < 2; i++)
#pragma unroll
        for (int j = 0; j < 4; j++)
            wmma::load_matrix_sync(acc[i][j], &BiasS[0][wn * 64 + j * 16], 132, wmma::mem_row_major);
    __syncthreads();

    {
        cpasync16(&Ah[0][ar0][ac0], &Ag[(size_t)ar0 * E_ + ac0]);
        cpasync16(&Ah[0][ar1][ac1], &Ag[(size_t)ar1 * E_ + ac1]);
        cpasync16(&Bh[0][br0][bc0], &Bg[(size_t)br0 * E_ + bc0]);
        cpasync16(&Bh[0][br1][bc1], &Bg[(size_t)br1 * E_ + bc1]);
    }
    CP_COMMIT();

    for (int it = 0; it < OKH_NIT; it++) {
        const int cur = it & 1;
        if (it + 1 < OKH_NIT) {
            const int nxt = cur ^ 1;
            const int k0 = (it + 1) * OKH_TK;
            cpasync16(&Ah[nxt][ar0][ac0], &Ag[(size_t)ar0 * E_ + k0 + ac0]);
            cpasync16(&Ah[nxt][ar1][ac1], &Ag[(size_t)ar1 * E_ + k0 + ac1]);
            cpasync16(&Bh[nxt][br0][bc0], &Bg[(size_t)(k0 + br0) * E_ + bc0]);
            cpasync16(&Bh[nxt][br1][bc1], &Bg[(size_t)(k0 + br1) * E_ + bc1]);
        }
        CP_COMMIT();
        CP_WAIT(1);
        __syncthreads();

#pragma unroll
        for (int kk = 0; kk < OKH_TK / 16; kk++) {
            AFragH a[2];
#pragma unroll
            for (int i = 0; i < 2; i++)
                wmma::load_matrix_sync(a[i], &Ah[cur][wm * 32 + i * 16][kk * 16], 40);
#pragma unroll
            for (int j = 0; j < 4; j++) {
                BFragH bfr;
                wmma::load_matrix_sync(bfr, &Bh[cur][kk * 16][wn * 64 + j * 16], 136);
#pragma unroll
                for (int i = 0; i < 2; i++) wmma::mma_sync(acc[i][j], a[i], bfr, acc[i][j]);
            }
        }
        __syncthreads();
    }

#pragma unroll
    for (int i = 0; i < 2; i++)
#pragma unroll
        for (int j = 0; j < 4; j++)
            wmma::store_matrix_sync(out + (size_t)(row0 + wm * 32 + i * 16) * E_ + col0 + wn * 64 + j * 16,
                                    acc[i][j], E_, wmma::mem_row_major);
}

// ===========================================================================
extern "C" void kernel_launch(void* const* d_in, const int* in_sizes, int n_in,
                              void* d_out, int out_size) {
    const float* x  = (const float*)d_in[0];
    const float* Wq = (const float*)d_in[1];
    const float* Wk = (const float*)d_in[2];
    const float* Wv = (const float*)d_in[3];
    const float* Wo = (const float*)d_in[4];
    const float* bo = (const float*)d_in[5];
    float* out = (float*)d_out;

    wo_half_kernel<<<1024, 256>>>((const float4*)Wo);
    fused_kv_kernel<<<dim3(NCHUNK_, BH_), 256>>>(x, Wk, Wv);
    reduce_kernel<<<BH_, 256>>>();
    fused_ctx_kernel<<<dim3(S_ / 32, BH_), 256>>>(x, Wq);
    out_kernel<<<dim3(E_ / 128, (B_ * S_) / 128), 256>>>(bo, out);
}

// round 10
// speedup vs baseline: 5.9077x; 1.6451x over previous
#include <cuda_runtime.h>
#include <mma.h>
#include <cuda_fp16.h>
#include <cstdint>

using namespace nvcuda;

#define B_  8
#define S_  2048
#define E_  2048
#define H_  16
#define D_  128
#define BH_ (B_ * H_)
#define NCHUNK_ 4
#define CHUNK_S_ (S_ / NCHUNK_)   // 512
#define EPS_ 1e-6f
#define DEN_SCALE_ 4096.0f
#define INV_DEN_SCALE_ (1.0f / 4096.0f)

// tf32 fragments (fused_kv phase 2 only)
typedef wmma::fragment<wmma::matrix_a, 16, 16, 8, wmma::precision::tf32, wmma::col_major> ATFrag;
typedef wmma::fragment<wmma::matrix_b, 16, 16, 8, wmma::precision::tf32, wmma::row_major> BFrag;
typedef wmma::fragment<wmma::accumulator, 16, 16, 8, float> CFrag;
// fp16 fragments
typedef wmma::fragment<wmma::matrix_a, 16, 16, 16, __half, wmma::row_major> AFragH;
typedef wmma::fragment<wmma::matrix_b, 16, 16, 16, __half, wmma::row_major> BFragH;
typedef wmma::fragment<wmma::accumulator, 16, 16, 16, float> CFragH;

__device__ __forceinline__ float phi_(float y) { return (y > 0.f) ? (y + 1.f) : expf(y); }
__device__ __forceinline__ float rtf32_(float y) { return wmma::__float_to_tf32(y); }

// load float4 from gmem value, store 4 halves (8B) to smem
__device__ __forceinline__ void f4_to_h4(__half* smem, const float4 v) {
    __half2 h0 = __floats2half2_rn(v.x, v.y);
    __half2 h1 = __floats2half2_rn(v.z, v.w);
    uint2 u;
    u.x = *(uint32_t*)&h0;
    u.y = *(uint32_t*)&h1;
    *(uint2*)smem = u;
}

__device__ __forceinline__ void cpasync16(void* smem, const void* gmem) {
    uint32_t s = (uint32_t)__cvta_generic_to_shared(smem);
    asm volatile("cp.async.cg.shared.global [%0], [%1], 16;" :: "r"(s), "l"(gmem));
}
#define CP_COMMIT()  asm volatile("cp.async.commit_group;")
#define CP_WAIT(N)   asm volatile("cp.async.wait_group %0;" :: "n"(N))

// ---------------- scratch (__device__ globals; no allocation allowed) ----------------
__device__ float  g_kvp[(size_t)BH_ * NCHUNK_ * D_ * D_];   // 32 MB fp32 partial kv
__device__ float  g_ksp[(size_t)BH_ * NCHUNK_ * D_];
__device__ __half g_kvh[(size_t)BH_ * D_ * D_];             // 4 MB fp16 kv
__device__ float  g_ks [(size_t)BH_ * D_];
__device__ __half g_combh[(size_t)B_ * S_ * E_];            // 64 MB fp16 combined heads
__device__ __half g_woh [(size_t)E_ * E_];                  // 8 MB fp16 Wo

// ===========================================================================
// Prep: convert Wo -> fp16.
// ===========================================================================
__global__ void wo_half_kernel(const float4* __restrict__ src) {
    const int n4 = (E_ * E_) / 4;
    int i = blockIdx.x * blockDim.x + threadIdx.x;
    int stride = gridDim.x * blockDim.x;
    for (; i < n4; i += stride) {
        float4 v = src[i];
        __half2* d = (__half2*)&g_woh[(size_t)i * 4];
        d[0] = __floats2half2_rn(v.x, v.y);
        d[1] = __floats2half2_rn(v.z, v.w);
    }
}

// ===========================================================================
// Kernel A: fused K-proj, V-proj (fp16 mma), phi, partial kv (tf32) & ksum.
// grid = (NCHUNK, BH), block 256 (8 warps). 32-row sub-tiles.
// ===========================================================================
union KvSmem {
    struct { __half XsH[32][40]; __half WkH[32][136]; __half WvH[32][136]; } p1;  // ~20 KB
    struct { float Kt[32][132]; float Vt[32][132]; } p2;                          // ~33.8 KB
};

__global__ void __launch_bounds__(256) fused_kv_kernel(const float* __restrict__ x,
                                                       const float* __restrict__ Wk,
                                                       const float* __restrict__ Wv) {
    __shared__ KvSmem sm;

    const int chunk = blockIdx.x;
    const int bh    = blockIdx.y;
    const int b = bh / H_, h = bh % H_;

    const float* Wkh = Wk + (size_t)h * D_ * D_;
    const float* Wvh = Wv + (size_t)h * D_ * D_;
    const float* Xb  = x + (size_t)b * S_ * E_ + (size_t)h * D_;

    const int tid  = threadIdx.x;
    const int warp = tid >> 5;
    const int lane = tid & 31;
    const int wm1 = warp & 1;    // 16-row blocks
    const int wn1 = warp >> 1;   // 32-col blocks
    const int wm2 = warp & 3;    // phase2: 32-row blocks
    const int wn2 = warp >> 2;   // phase2: 64-col blocks

    CFrag acc_kv[2][4];
#pragma unroll
    for (int i = 0; i < 2; i++)
#pragma unroll
        for (int j = 0; j < 4; j++) wmma::fill_fragment(acc_kv[i][j], 0.f);

    float ksum_acc = 0.f;

    for (int sub = 0; sub < CHUNK_S_ / 32; sub++) {
        const int s0 = chunk * CHUNK_S_ + sub * 32;

        // ---- phase 1 (fp16): Kt/Vt(32x128) = X(32x128) @ Wk/Wv ----
        CFragH acck[2], accv[2];
#pragma unroll
        for (int j = 0; j < 2; j++) { wmma::fill_fragment(acck[j], 0.f); wmma::fill_fragment(accv[j], 0.f); }

        for (int k0 = 0; k0 < D_; k0 += 32) {
            {   // X chunk 32x32 -> half
                int r = tid >> 3, c4 = (tid & 7) * 4;
                f4_to_h4(&sm.p1.XsH[r][c4], *(const float4*)&Xb[(size_t)(s0 + r) * E_ + k0 + c4]);
            }
#pragma unroll
            for (int t = 0; t < 4; t++) {   // Wk,Wv chunks 32x128 -> half
                int f4i = tid + t * 256;
                int r = f4i >> 5, c4 = (f4i & 31) * 4;
                f4_to_h4(&sm.p1.WkH[r][c4], *(const float4*)&Wkh[(size_t)(k0 + r) * D_ + c4]);
                f4_to_h4(&sm.p1.WvH[r][c4], *(const float4*)&Wvh[(size_t)(k0 + r) * D_ + c4]);
            }
            __syncthreads();
#pragma unroll
            for (int kk = 0; kk < 2; kk++) {
                AFragH a;
                wmma::load_matrix_sync(a, &sm.p1.XsH[wm1 * 16][kk * 16], 40);
#pragma unroll
                for (int j = 0; j < 2; j++) {
                    BFragH bfr;
                    wmma::load_matrix_sync(bfr, &sm.p1.WkH[kk * 16][wn1 * 32 + j * 16], 136);
                    wmma::mma_sync(acck[j], a, bfr, acck[j]);
                    wmma::load_matrix_sync(bfr, &sm.p1.WvH[kk * 16][wn1 * 32 + j * 16], 136);
                    wmma::mma_sync(accv[j], a, bfr, accv[j]);
                }
            }
            __syncthreads();
        }
        // p1 dead; write phi(K), V (tf32-rounded) into overlapping p2 float tiles
#pragma unroll
        for (int j = 0; j < 2; j++) {
#pragma unroll
            for (int e = 0; e < acck[j].num_elements; e++) acck[j].x[e] = rtf32_(phi_(acck[j].x[e]));
#pragma unroll
            for (int e = 0; e < accv[j].num_elements; e++) accv[j].x[e] = rtf32_(accv[j].x[e]);
            wmma::store_matrix_sync(&sm.p2.Kt[wm1 * 16][wn1 * 32 + j * 16], acck[j], 132, wmma::mem_row_major);
            wmma::store_matrix_sync(&sm.p2.Vt[wm1 * 16][wn1 * 32 + j * 16], accv[j], 132, wmma::mem_row_major);
        }
        __syncthreads();

        // ---- ksum partial ----
        if (warp < 4) {
            const int col = warp * 32 + lane;
#pragma unroll 8
            for (int r = 0; r < 32; r++) ksum_acc += sm.p2.Kt[r][col];
        }

        // ---- phase 2 (tf32): kv += Kt^T @ Vt ----
#pragma unroll
        for (int kk = 0; kk < 4; kk++) {
            ATFrag a2[2];
#pragma unroll
            for (int i = 0; i < 2; i++)
                wmma::load_matrix_sync(a2[i], &sm.p2.Kt[kk * 8][wm2 * 32 + i * 16], 132);
#pragma unroll
            for (int j = 0; j < 4; j++) {
                BFrag bfr;
                wmma::load_matrix_sync(bfr, &sm.p2.Vt[kk * 8][wn2 * 64 + j * 16], 132);
#pragma unroll
                for (int i = 0; i < 2; i++) wmma::mma_sync(acc_kv[i][j], a2[i], bfr, acc_kv[i][j]);
            }
        }
        __syncthreads();
    }

    float* kvp = g_kvp + ((size_t)bh * NCHUNK_ + chunk) * D_ * D_;
#pragma unroll
    for (int i = 0; i < 2; i++)
#pragma unroll
        for (int j = 0; j < 4; j++)
            wmma::store_matrix_sync(&kvp[(size_t)(wm2 * 32 + i * 16) * D_ + wn2 * 64 + j * 16],
                                    acc_kv[i][j], D_, wmma::mem_row_major);
    if (warp < 4)
        g_ksp[((size_t)bh * NCHUNK_ + chunk) * D_ + warp * 32 + lane] = ksum_acc;
}

// ===========================================================================
// Kernel A2: reduce the NCHUNK partials; kv -> fp16.
// ===========================================================================
__global__ void reduce_kernel() {
    const int bh = blockIdx.x;
    const int tid = threadIdx.x;
    const float* kvp = g_kvp + (size_t)bh * NCHUNK_ * D_ * D_;
    __half* kv = g_kvh + (size_t)bh * D_ * D_;
    for (int i = tid; i < D_ * D_; i += 256) {
        float s = 0.f;
#pragma unroll
        for (int c = 0; c < NCHUNK_; c++) s += kvp[(size_t)c * D_ * D_ + i];
        kv[i] = __float2half_rn(s);
    }
    if (tid < D_) {
        const float* ksp = g_ksp + (size_t)bh * NCHUNK_ * D_;
        float s = 0.f;
#pragma unroll
        for (int c = 0; c < NCHUNK_; c++) s += ksp[(size_t)c * D_ + tid];
        g_ks[(size_t)bh * D_ + tid] = s;
    }
}

// ===========================================================================
// Kernel B: fused Q-proj + phi + ctx, all-fp16 mma.  grid = (S/32, BH), 256 thr.
// Qt scaled by 4096/(den+eps) to stay in fp16-normal range; epilogue * 1/4096.
// ===========================================================================
union CtxU {
    struct { __half XsH[32][40]; __half WH[32][136]; } p1;     // ~11.2 KB
    struct { __half QtH[32][136]; __half kvH[32][136]; } p2;   // ~17.4 KB
};

__global__ void __launch_bounds__(256) fused_ctx_kernel(const float* __restrict__ x,
                                                        const float* __restrict__ Wq) {
    __shared__ float QtF[32][132];   // fp32 Qt (phase 1 result), reused as ctx stage
    __shared__ CtxU u;
    __shared__ float ksum_s[128];
    __shared__ float den_s[32];

    const int stile = blockIdx.x;
    const int bh    = blockIdx.y;
    const int b = bh / H_, h = bh % H_;

    const float* Wqh = Wq + (size_t)h * D_ * D_;
    const float* Xb  = x + (size_t)b * S_ * E_ + (size_t)h * D_;
    const __half* kv = g_kvh + (size_t)bh * D_ * D_;

    const int tid  = threadIdx.x;
    const int warp = tid >> 5;
    const int wm = warp & 1;
    const int wn = warp >> 1;
    const int s0 = stile * 32;

    if (tid < 128) ksum_s[tid] = g_ks[(size_t)bh * D_ + tid];

    // ---- phase 1 (fp16): Qt = phi(X @ Wq) -> QtF (float) ----
    CFragH acc[2];
#pragma unroll
    for (int j = 0; j < 2; j++) wmma::fill_fragment(acc[j], 0.f);

    for (int k0 = 0; k0 < D_; k0 += 32) {
        {
            int r = tid >> 3, c4 = (tid & 7) * 4;
            f4_to_h4(&u.p1.XsH[r][c4], *(const float4*)&Xb[(size_t)(s0 + r) * E_ + k0 + c4]);
        }
#pragma unroll
        for (int t = 0; t < 4; t++) {
            int f4i = tid + t * 256;
            int r = f4i >> 5, c4 = (f4i & 31) * 4;
            f4_to_h4(&u.p1.WH[r][c4], *(const float4*)&Wqh[(size_t)(k0 + r) * D_ + c4]);
        }
        __syncthreads();
#pragma unroll
        for (int kk = 0; kk < 2; kk++) {
            AFragH a;
            wmma::load_matrix_sync(a, &u.p1.XsH[wm * 16][kk * 16], 40);
#pragma unroll
            for (int j = 0; j < 2; j++) {
                BFragH bfr;
                wmma::load_matrix_sync(bfr, &u.p1.WH[kk * 16][wn * 32 + j * 16], 136);
                wmma::mma_sync(acc[j], a, bfr, acc[j]);
            }
        }
        __syncthreads();
    }
#pragma unroll
    for (int j = 0; j < 2; j++) {
#pragma unroll
        for (int e = 0; e < acc[j].num_elements; e++) acc[j].x[e] = phi_(acc[j].x[e]);
        wmma::store_matrix_sync(&QtF[wm * 16][wn * 32 + j * 16], acc[j], 132, wmma::mem_row_major);
    }
    __syncthreads();

    // ---- den from QtF; scaled-convert Qt -> QtH (fp16, p1 now dead) ----
    if (tid < 32) {
        float dsum = 0.f;
#pragma unroll
        for (int c = 0; c < 128; c++) dsum = fmaf(QtF[tid][c], ksum_s[c], dsum);
        den_s[tid] = DEN_SCALE_ / (dsum + EPS_);
    }
    __syncthreads();
#pragma unroll
    for (int t = 0; t < 8; t++) {
        int i = tid + t * 256;            // 0..2047 -> 32 rows x 64 half2
        int r = i >> 6, c2 = i & 63;
        float sc = den_s[r];
        *(__half2*)&u.p2.QtH[r][c2 * 2] =
            __floats2half2_rn(QtF[r][c2 * 2] * sc, QtF[r][c2 * 2 + 1] * sc);
    }
    __syncthreads();

    // ---- phase 2 (fp16): ctx = QtH @ kvH ----
#pragma unroll
    for (int j = 0; j < 2; j++) wmma::fill_fragment(acc[j], 0.f);

    for (int k0 = 0; k0 < D_; k0 += 32) {
#pragma unroll
        for (int t = 0; t < 4; t++) {     // kv chunk 32x128 half
            int f = tid + t * 256;
            int r = f >> 5, c4 = (f & 31) * 4;
            *(uint2*)&u.p2.kvH[r][c4] = *(const uint2*)&kv[(size_t)(k0 + r) * D_ + c4];
        }
        __syncthreads();
#pragma unroll
        for (int kk = 0; kk < 2; kk++) {
            AFragH a;
            wmma::load_matrix_sync(a, &u.p2.QtH[wm * 16][k0 + kk * 16], 136);
#pragma unroll
            for (int j = 0; j < 2; j++) {
                BFragH bfr;
                wmma::load_matrix_sync(bfr, &u.p2.kvH[kk * 16][wn * 32 + j * 16], 136);
                wmma::mma_sync(acc[j], a, bfr, acc[j]);
            }
        }
        __syncthreads();
    }

    // ---- epilogue: stage ctx in QtF, write fp16 g_combh (undo 4096 scale) ----
#pragma unroll
    for (int j = 0; j < 2; j++)
        wmma::store_matrix_sync(&QtF[wm * 16][wn * 32 + j * 16], acc[j], 132, wmma::mem_row_major);
    __syncthreads();
#pragma unroll
    for (int t = 0; t < 8; t++) {
        int i = tid + t * 256;
        int r = i >> 6, c2 = i & 63;
        __half2 v = __floats2half2_rn(QtF[r][c2 * 2] * INV_DEN_SCALE_,
                                      QtF[r][c2 * 2 + 1] * INV_DEN_SCALE_);
        *(__half2*)&g_combh[((size_t)(b * S_ + s0 + r)) * E_ + h * D_ + c2 * 2] = v;
    }
}

// ===========================================================================
// Kernel C: out = g_combh @ g_woh + bo (fp16 wmma m16n16k16, fp32 accum).
// (unchanged from passing round 9)
// ===========================================================================
#define OKH_TK 32
#define OKH_NIT (E_ / OKH_TK)   // 64

__global__ void __launch_bounds__(256, 2) out_kernel(const float* __restrict__ bo,
                                                     float* __restrict__ out) {
    __shared__ __align__(16) __half Ah[2][128][40];
    __shared__ __align__(16) __half Bh[2][OKH_TK][136];
    __shared__ __align__(16) float BiasS[16][132];

    const int col0 = blockIdx.x * 128;
    const int row0 = blockIdx.y * 128;
    const int tid  = threadIdx.x;
    const int warp = tid >> 5;
    const int wm = warp & 3;
    const int wn = warp >> 2;

    const int ar0 = tid >> 2,         ac0 = (tid & 3) * 8;
    const int ar1 = (tid + 256) >> 2, ac1 = ac0;
    const int br0 = tid >> 4,         bc0 = (tid & 15) * 8;
    const int br1 = (tid + 256) >> 4, bc1 = bc0;

    const __half* Ag = g_combh + (size_t)row0 * E_;
    const __half* Bg = g_woh + (size_t)col0;

#pragma unroll
    for (int t = 0; t < 8; t++) {
        int i = tid + t * 256;
        int r = i >> 7, c = i & 127;
        BiasS[r][c] = bo[col0 + c];
    }
    __syncthreads();

    CFragH acc[2][4];
#pragma unroll
    for (int i = 0; i < 2; i++)
#pragma unroll
        for (int j = 0; j < 4; j++)
            wmma::load_matrix_sync(acc[i][j], &BiasS[0][wn * 64 + j * 16], 132, wmma::mem_row_major);
    __syncthreads();

    {
        cpasync16(&Ah[0][ar0][ac0], &Ag[(size_t)ar0 * E_ + ac0]);
        cpasync16(&Ah[0][ar1][ac1], &Ag[(size_t)ar1 * E_ + ac1]);
        cpasync16(&Bh[0][br0][bc0], &Bg[(size_t)br0 * E_ + bc0]);
        cpasync16(&Bh[0][br1][bc1], &Bg[(size_t)br1 * E_ + bc1]);
    }
    CP_COMMIT();

    for (int it = 0; it < OKH_NIT; it++) {
        const int cur = it & 1;
        if (it + 1 < OKH_NIT) {
            const int nxt = cur ^ 1;
            const int k0 = (it + 1) * OKH_TK;
            cpasync16(&Ah[nxt][ar0][ac0], &Ag[(size_t)ar0 * E_ + k0 + ac0]);
            cpasync16(&Ah[nxt][ar1][ac1], &Ag[(size_t)ar1 * E_ + k0 + ac1]);
            cpasync16(&Bh[nxt][br0][bc0], &Bg[(size_t)(k0 + br0) * E_ + bc0]);
            cpasync16(&Bh[nxt][br1][bc1], &Bg[(size_t)(k0 + br1) * E_ + bc1]);
        }
        CP_COMMIT();
        CP_WAIT(1);
        __syncthreads();

#pragma unroll
        for (int kk = 0; kk < OKH_TK / 16; kk++) {
            AFragH a[2];
#pragma unroll
            for (int i = 0; i < 2; i++)
                wmma::load_matrix_sync(a[i], &Ah[cur][wm * 32 + i * 16][kk * 16], 40);
#pragma unroll
            for (int j = 0; j < 4; j++) {
                BFragH bfr;
                wmma::load_matrix_sync(bfr, &Bh[cur][kk * 16][wn * 64 + j * 16], 136);
#pragma unroll
                for (int i = 0; i < 2; i++) wmma::mma_sync(acc[i][j], a[i], bfr, acc[i][j]);
            }
        }
        __syncthreads();
    }

#pragma unroll
    for (int i = 0; i < 2; i++)
#pragma unroll
        for (int j = 0; j < 4; j++)
            wmma::store_matrix_sync(out + (size_t)(row0 + wm * 32 + i * 16) * E_ + col0 + wn * 64 + j * 16,
                                    acc[i][j], E_, wmma::mem_row_major);
}

// ===========================================================================
extern "C" void kernel_launch(void* const* d_in, const int* in_sizes, int n_in,
                              void* d_out, int out_size) {
    const float* x  = (const float*)d_in[0];
    const float* Wq = (const float*)d_in[1];
    const float* Wk = (const float*)d_in[2];
    const float* Wv = (const float*)d_in[3];
    const float* Wo = (const float*)d_in[4];
    const float* bo = (const float*)d_in[5];
    float* out = (float*)d_out;

    wo_half_kernel<<<1024, 256>>>((const float4*)Wo);
    fused_kv_kernel<<<dim3(NCHUNK_, BH_), 256>>>(x, Wk, Wv);
    reduce_kernel<<<BH_, 256>>>();
    fused_ctx_kernel<<<dim3(S_ / 32, BH_), 256>>>(x, Wq);
    out_kernel<<<dim3(E_ / 128, (B_ * S_) / 128), 256>>>(bo, out);
}